// round 13
// baseline (speedup 1.0000x reference)
#include <cuda_runtime.h>
#include <cuda_fp16.h>
#include <math.h>
#include <stdint.h>

// Problem dims
#define NB 4096
#define TT 128
#define KV 64
#define EE 35
#define LL 200
#define GE3 105
#define LE 235

#define NTH 800    // 25 warps
#define BBLK 16    // batch rows per CTA (halved -> 2 CTAs/SM)
#define NCTA (NB / BBLK)   // 256

// fp16 m16n8k16, k16-PAIR packed B
#define NP0 2
#define NPH 7
#define NTILES 75

// Output layout: concat(pred[B,T,K], mu[B,L], logvar[B,L], predY[B,1])
#define PRED_OFF ((size_t)0)
#define MU_OFF   ((size_t)NB * TT * KV)
#define LV_OFF   (MU_OFF + (size_t)NB * LL)
#define PY_OFF   (LV_OFF + (size_t)NB * LL)

__device__ uint4 g_b0ih[NTILES * NP0 * 32];
__device__ uint4 g_b0hh[NTILES * NPH * 32];
__device__ uint4 g_b1ih[NTILES * NPH * 32];
__device__ uint4 g_b1hh[NTILES * NPH * 32];

// SMEM layout (floats), 16-batch: 26176 floats = 104.7KB  -> 2 CTAs/SM
#define HPAD 20
#define OFF_EMB 0        // 2240
#define OFF_CB  2240     // 1600
#define OFF_H1  3840     // 4000 (200 x 20 fp32)
#define OFF_H2  7840     // 4000
#define OFF_AXE 11840    // 1536 (4 k16 x 32 x 12)
#define OFF_AH1 13376    // 5376 (14 x 32 x 12)
#define OFF_AH2 18752    // 5376
#define OFF_TOK 24128    // 2048 (128 x 16)
#define SMEM_FLOATS 26176
// ---- post-encoder overlays (regions dead at time of use) ----
#define OFF_MUS 0        // 3200 (dead before weight staging)
#define OFF_W0  0        // 3675 dW_ih0[:,L:]
#define OFF_W1  3680     // 3675 dW_ih1 (over dead h1s)
#define OFF_T1  7840     // 3200 (over h2s, after h2s reads)
#define OFF_F2T 11840    // 2240 fc2^T (over axe)
#define OFF_ZS  14080    // 3200 (over ah1)
#define OFF_GZ  18752    // 1680 (over ah2)
#define OFF_G1  20432    // 1680
#define OFF_HD  22112    // 560
#define OFF_LW  22672    // 560 -> ends 23232

// Fast transcendentals (MUFU-based)
__device__ __forceinline__ float sigm(float v) {
    return __fdividef(1.0f, 1.0f + __expf(-v));
}
__device__ __forceinline__ float tanh_fast(float x) {
    float e = __expf(2.0f * x);
    return fmaf(-2.0f, __fdividef(1.0f, e + 1.0f), 1.0f);
}

__device__ __forceinline__ void mma16(float (&c)[4], const uint32_t (&a)[4], uint2 b) {
    asm volatile(
        "mma.sync.aligned.m16n8k16.row.col.f32.f16.f16.f32 "
        "{%0,%1,%2,%3}, {%4,%5,%6,%7}, {%8,%9}, {%0,%1,%2,%3};"
        : "+f"(c[0]), "+f"(c[1]), "+f"(c[2]), "+f"(c[3])
        : "r"(a[0]), "r"(a[1]), "r"(a[2]), "r"(a[3]), "r"(b.x), "r"(b.y));
}

__device__ __forceinline__ uint32_t h2bits(float lo, float hi) {
    __half2 h = __floats2half2_rn(lo, hi);
    return *(uint32_t*)&h;
}

// ---- prep: pack weights into paired-k16 fp16 B-fragment layout (unchanged) ----
__global__ void pack_b16(const float* __restrict__ s0, const float* __restrict__ s1,
                         const float* __restrict__ s2, const float* __restrict__ s3) {
    int m = blockIdx.y;
    const float* src = (m == 0) ? s0 : (m == 1) ? s1 : (m == 2) ? s2 : s3;
    uint4* dst = (m == 0) ? g_b0ih : (m == 1) ? g_b0hh : (m == 2) ? g_b1ih : g_b1hh;
    int K  = (m == 0) ? EE : LL;
    int np = (m == 0) ? NP0 : NPH;
    int idx = blockIdx.x * blockDim.x + threadIdx.x;
    int total = NTILES * np * 32;
    if (idx >= total) return;
    int lane = idx & 31;
    int r = idx >> 5;
    int kp = r % np;  r /= np;
    int tile = r;
    int gid = lane >> 2, tig = lane & 3;
    int n = tile * 8 + gid;
    float w[8];
    #pragma unroll
    for (int half = 0; half < 2; half++) {
        int kA = (2 * kp + half) * 16 + 2 * tig;
        w[half * 4 + 0] = (kA     < K) ? src[n * K + kA]     : 0.0f;
        w[half * 4 + 1] = (kA + 1 < K) ? src[n * K + kA + 1] : 0.0f;
        w[half * 4 + 2] = (kA + 8 < K) ? src[n * K + kA + 8] : 0.0f;
        w[half * 4 + 3] = (kA + 9 < K) ? src[n * K + kA + 9] : 0.0f;
    }
    dst[idx] = make_uint4(h2bits(w[0], w[1]), h2bits(w[2], w[3]),
                          h2bits(w[4], w[5]), h2bits(w[6], w[7]));
}

// MMA pass, single m-tile (16 batch): per kp = 3 B LDG.128 + 2 A LDS.128 + 6 mma
__device__ __forceinline__ void enc_pass(const uint32_t* __restrict__ atfA,
                                         const uint4* __restrict__ B, int np,
                                         float (&cr)[4], float (&cz)[4], float (&cn)[4],
                                         int wrp, int lane)
{
    const uint4* pr = B + (size_t)(wrp * np) * 32 + lane;
    const uint4* pz = pr + (size_t)25 * np * 32;
    const uint4* pn = pz + (size_t)25 * np * 32;
    #pragma unroll 1
    for (int kp = 0; kp < np; kp++) {
        uint4 br = pr[kp * 32];
        uint4 bz = pz[kp * 32];
        uint4 bn = pn[kp * 32];
        const uint32_t* p0 = atfA + ((2 * kp) * 32 + lane) * 12;
        const uint32_t* p1 = p0 + 32 * 12;
        uint4 v0 = *(const uint4*)p0;   // k16 even: a0..a3
        uint4 v1 = *(const uint4*)p1;   // k16 odd
        uint32_t ae[4] = {v0.x, v0.y, v0.z, v0.w};
        uint32_t ao[4] = {v1.x, v1.y, v1.z, v1.w};
        uint2 bre = make_uint2(br.x, br.y), bro = make_uint2(br.z, br.w);
        uint2 bze = make_uint2(bz.x, bz.y), bzo = make_uint2(bz.z, bz.w);
        uint2 bne = make_uint2(bn.x, bn.y), bno = make_uint2(bn.z, bn.w);
        mma16(cr, ae, bre);
        mma16(cz, ae, bze);
        mma16(cn, ae, bne);
        mma16(cr, ao, bro);
        mma16(cz, ao, bzo);
        mma16(cn, ao, bno);
    }
}

// Register GRU epilogue, single m-tile. c mapping: c[bh*2+d] = (b = bh*8+gid, j = j0+d).
// Fragment write: word (khalf*2 + bh) at lane slot = a-frag layout the consumer reads.
__device__ __forceinline__ void gru_epi(float* __restrict__ hb, uint32_t* __restrict__ atf_dst,
                                        const float* __restrict__ cb,
                                        float (&cr)[4], float (&cz)[4],
                                        float (&ci)[4], float (&ch)[4],
                                        int wrp, int lane)
{
    int gid = lane >> 2, tig = lane & 3;
    int j0 = 8 * wrp + 2 * tig;
    int k16d = wrp >> 1, khalf = wrp & 1;
    uint32_t* dst = atf_dst + (k16d * 32 + lane) * 12 + khalf * 2;
    float br0 = cb[j0], br1 = cb[j0 + 1];
    float bz0 = cb[200 + j0], bz1 = cb[200 + j0 + 1];
    float bi0 = cb[400 + j0], bi1 = cb[400 + j0 + 1];
    float bh0 = cb[600 + j0], bh1 = cb[600 + j0 + 1];
    uint32_t w[2];
    #pragma unroll
    for (int bh = 0; bh < 2; bh++) {
        int b = bh * 8 + gid;
        float hv[2];
        #pragma unroll
        for (int d = 0; d < 2; d++) {
            int i = bh * 2 + d;
            int j = j0 + d;
            float r = sigm(cr[i] + (d ? br1 : br0));
            float z = sigm(cz[i] + (d ? bz1 : bz0));
            float n = tanh_fast(ci[i] + (d ? bi1 : bi0) + r * (ch[i] + (d ? bh1 : bh0)));
            float ho = hb[j * HPAD + b];
            float hn = n + z * (ho - n);
            hb[j * HPAD + b] = hn;
            hv[d] = hn;
        }
        w[bh] = h2bits(hv[0], hv[1]);
    }
    *(uint2*)dst = make_uint2(w[0], w[1]);
}

extern "C" __global__ void __launch_bounds__(NTH, 2)
vae_all(const int* __restrict__ x, const float* __restrict__ emb,
        const float* __restrict__ eb_ih0, const float* __restrict__ eb_hh0,
        const float* __restrict__ eb_ih1, const float* __restrict__ eb_hh1,
        const float* __restrict__ dW_ih0, const float* __restrict__ db_ih0,
        const float* __restrict__ db_hh0,
        const float* __restrict__ dW_ih1, const float* __restrict__ db_ih1,
        const float* __restrict__ db_hh1,
        const float* __restrict__ fc11_w, const float* __restrict__ fc11_b,
        const float* __restrict__ fc12_w, const float* __restrict__ fc12_b,
        const float* __restrict__ p1_w,  const float* __restrict__ p1_b,
        const float* __restrict__ p2_w,  const float* __restrict__ p2_b,
        const float* __restrict__ fc2_w, const float* __restrict__ fc2_b,
        const float* __restrict__ eps,   float* __restrict__ out)
{
    extern __shared__ float sm[];
    float* emb_s = sm + OFF_EMB;
    float* cb_s  = sm + OFF_CB;
    float* h1s   = sm + OFF_H1;
    float* h2s   = sm + OFF_H2;
    uint32_t* axe = (uint32_t*)(sm + OFF_AXE);
    uint32_t* ah1 = (uint32_t*)(sm + OFF_AH1);
    uint32_t* ah2 = (uint32_t*)(sm + OFF_AH2);
    int* toks = (int*)(sm + OFF_TOK);

    const int tid = threadIdx.x;
    const int bg0 = blockIdx.x * BBLK;

    for (int i = tid; i < KV * EE; i += NTH) emb_s[i] = emb[i];
    for (int i = tid; i < LL * HPAD; i += NTH) { h1s[i] = 0.0f; h2s[i] = 0.0f; }
    for (int i = tid; i < 4 * 32 * 12; i += NTH) axe[i] = 0u;
    for (int i = tid; i < 14 * 32 * 12; i += NTH) { ah1[i] = 0u; ah2[i] = 0u; }
    for (int i = tid; i < TT * BBLK; i += NTH) {
        int t = i >> 4, b = i & 15;
        toks[i] = x[(size_t)(bg0 + b) * TT + t];
    }
    for (int i = tid; i < 1600; i += NTH) {
        int l = i / 800, rem = i % 800, g = rem / 200, j = rem % 200;
        const float* bi = l ? eb_ih1 : eb_ih0;
        const float* bh = l ? eb_hh1 : eb_hh0;
        float v;
        if      (g == 0) v = bi[j] + bh[j];
        else if (g == 1) v = bi[200 + j] + bh[200 + j];
        else if (g == 2) v = bi[400 + j];
        else             v = bh[400 + j];
        cb_s[i] = v;
    }
    __syncthreads();

    const int lane = tid & 31;
    const int wrp  = tid >> 5;

    // heads/decoder elementwise mapping: one j per thread, 4 batch per thread
    const int j0e = tid >> 2;        // 0..199
    const int b0e = (tid & 3) * 4;   // 0,4,8,12

    // =====================  ENCODER (fp16 mma, 16-batch)  =====================
    for (int t = 0; t < TT; t++) {
        if (tid < 288) {   // 18 k-pairs x 16 batch
            int kp = tid >> 4, b = tid & 15;
            int k = kp * 2;
            int tok = toks[t * 16 + b];
            float e0 = emb_s[tok * EE + k];
            float e1 = (k + 1 < EE) ? emb_s[tok * EE + k + 1] : 0.0f;
            int jj = k & 15, k16 = k >> 4;
            int tigp = (jj & 7) >> 1, khalf = jj >> 3;
            int bhalf = b >> 3, gidp = b & 7;
            axe[(k16 * 32 + gidp * 4 + tigp) * 12 + khalf * 2 + bhalf] = h2bits(e0, e1);
        }
        __syncthreads();

        {   // ---- layer 0 ----
            float cr[4] = {}, cz[4] = {}, ci[4] = {}, ch[4] = {};
            enc_pass(axe, g_b0ih, NP0, cr, cz, ci, wrp, lane);
            enc_pass(ah1, g_b0hh, NPH, cr, cz, ch, wrp, lane);
            __syncthreads();
            gru_epi(h1s, ah1, cb_s, cr, cz, ci, ch, wrp, lane);
        }
        __syncthreads();
        {   // ---- layer 1 ----
            float cr[4] = {}, cz[4] = {}, ci[4] = {}, ch[4] = {};
            enc_pass(ah1, g_b1ih, NPH, cr, cz, ci, wrp, lane);
            enc_pass(ah2, g_b1hh, NPH, cr, cz, ch, wrp, lane);
            __syncthreads();
            gru_epi(h2s, ah2, cb_s + 800, cr, cz, ci, ch, wrp, lane);
        }
        __syncthreads();
    }

    float* mus   = sm + OFF_MUS;
    float* t1s   = sm + OFF_T1;
    float* zs    = sm + OFF_ZS;
    float* gzs   = sm + OFF_GZ;
    float* g1s   = sm + OFF_G1;
    float* hds   = sm + OFF_HD;
    float* lastw = sm + OFF_LW;
    float* w0s   = sm + OFF_W0;
    float* w1s   = sm + OFF_W1;
    float* f2t   = sm + OFF_F2T;

    // =====================  HEADS (1 j x 4 b per thread)  =====================
    {
        float am[4], al[4];
        {
            float bm = fc11_b[j0e], bl = fc12_b[j0e];
            #pragma unroll
            for (int b = 0; b < 4; b++) { am[b] = bm; al[b] = bl; }
        }
        const float* w1 = fc11_w + j0e * LL;
        const float* w2 = fc12_w + j0e * LL;
        #pragma unroll 1
        for (int k = 0; k < LL; k += 2) {
            float4 u = *(const float4*)(h2s + k * HPAD + b0e);
            float4 w = *(const float4*)(h2s + (k + 1) * HPAD + b0e);
            float va[4] = {u.x, u.y, u.z, u.w};
            float vb[4] = {w.x, w.y, w.z, w.w};
            float2 a = *(const float2*)(w1 + k);
            float2 c = *(const float2*)(w2 + k);
            #pragma unroll
            for (int b = 0; b < 4; b++) {
                am[b] = fmaf(a.x, va[b], am[b]);
                am[b] = fmaf(a.y, vb[b], am[b]);
                al[b] = fmaf(c.x, va[b], al[b]);
                al[b] = fmaf(c.y, vb[b], al[b]);
            }
        }
        __syncthreads();   // h2s reads done before overlays
        #pragma unroll
        for (int b = 0; b < 4; b++) {
            int j = j0e, bb = b0e + b, bg = bg0 + bb;
            float m = am[b], lv = al[b];
            out[MU_OFF + (size_t)bg * LL + j] = m;
            out[LV_OFF + (size_t)bg * LL + j] = lv;
            mus[j * 16 + bb] = m;
            zs[j * 16 + bb] = fmaf(eps[(size_t)bg * LL + j], expf(0.5f * lv), m);
        }
        __syncthreads();
    }
    {   // t1 = relu(mu @ p1^T + b)
        float aa[4];
        {
            float bv = p1_b[j0e];
            #pragma unroll
            for (int b = 0; b < 4; b++) aa[b] = bv;
        }
        const float* w1 = p1_w + j0e * LL;
        #pragma unroll 1
        for (int k = 0; k < LL; k += 2) {
            float4 u = *(const float4*)(mus + k * 16 + b0e);
            float4 w = *(const float4*)(mus + (k + 1) * 16 + b0e);
            float va[4] = {u.x, u.y, u.z, u.w};
            float vb[4] = {w.x, w.y, w.z, w.w};
            float2 a = *(const float2*)(w1 + k);
            #pragma unroll
            for (int b = 0; b < 4; b++) {
                aa[b] = fmaf(a.x, va[b], aa[b]);
                aa[b] = fmaf(a.y, vb[b], aa[b]);
            }
        }
        #pragma unroll
        for (int b = 0; b < 4; b++)
            t1s[j0e * 16 + b0e + b] = fmaxf(aa[b], 0.0f);
        __syncthreads();   // mus reads done -> weight staging may overwrite
    }
    if (tid < BBLK) {
        float a = p2_b[0];
        for (int j = 0; j < LL; j++) a = fmaf(p2_w[j], t1s[j * 16 + tid], a);
        out[PY_OFF + bg0 + tid] = a;
    }
    for (int idx = tid; idx < GE3 * 16; idx += NTH) {
        int g = idx >> 4, b = idx & 15;
        float a = db_ih0[g];
        const float* w = dW_ih0 + g * LE;
        #pragma unroll 4
        for (int k = 0; k < LL; k++) a = fmaf(zs[k * 16 + b], w[k], a);
        gzs[idx] = a;
    }
    for (int i = tid; i < GE3 * EE; i += NTH) {
        w0s[i] = dW_ih0[(i / EE) * LE + LL + (i % EE)];
        w1s[i] = dW_ih1[i];
    }
    for (int i = tid; i < EE * KV; i += NTH)
        f2t[i] = fc2_w[(i & 63) * EE + (i >> 6)];
    for (int i = tid; i < EE * 16; i += NTH) lastw[i] = 0.0f;
    __syncthreads();

    // =====================  DECODER (fp32 SIMT, 16-batch, float4)  =====================
    for (int t = 0; t < TT; t++) {
        // gi1 = gz + lastword @ dW_ih0[:, L:]^T
        for (int idx = tid; idx < GE3 * 4; idx += NTH) {
            int g = idx >> 2, b0 = (idx & 3) * 4;
            float4 acc = *(const float4*)(gzs + g * 16 + b0);
            const float* w = w0s + g * EE;
            #pragma unroll 5
            for (int k = 0; k < EE; k++) {
                float4 a = *(const float4*)(lastw + k * 16 + b0);
                float wv = w[k];
                acc.x = fmaf(wv, a.x, acc.x);
                acc.y = fmaf(wv, a.y, acc.y);
                acc.z = fmaf(wv, a.z, acc.z);
                acc.w = fmaf(wv, a.w, acc.w);
            }
            *(float4*)(g1s + g * 16 + b0) = acc;
        }
        __syncthreads();
        for (int idx = tid; idx < EE * 16; idx += NTH) {
            int e = idx >> 4, b = idx & 15;
            float r  = sigm(g1s[e * 16 + b] + db_hh0[e]);
            float zg = sigm(g1s[(EE + e) * 16 + b] + db_hh0[EE + e]);
            float n  = tanh_fast(fmaf(r, db_hh0[2 * EE + e], g1s[(2 * EE + e) * 16 + b]));
            hds[idx] = (1.0f - zg) * n;
        }
        __syncthreads();
        // gi2 = h1 @ dW_ih1^T + db_ih1
        for (int idx = tid; idx < GE3 * 4; idx += NTH) {
            int g = idx >> 2, b0 = (idx & 3) * 4;
            float bv = db_ih1[g];
            float4 acc = make_float4(bv, bv, bv, bv);
            const float* w = w1s + g * EE;
            #pragma unroll 5
            for (int k = 0; k < EE; k++) {
                float4 a = *(const float4*)(hds + k * 16 + b0);
                float wv = w[k];
                acc.x = fmaf(wv, a.x, acc.x);
                acc.y = fmaf(wv, a.y, acc.y);
                acc.z = fmaf(wv, a.z, acc.z);
                acc.w = fmaf(wv, a.w, acc.w);
            }
            *(float4*)(g1s + g * 16 + b0) = acc;
        }
        __syncthreads();
        for (int idx = tid; idx < EE * 16; idx += NTH) {
            int e = idx >> 4, b = idx & 15;
            float r  = sigm(g1s[e * 16 + b] + db_hh1[e]);
            float zg = sigm(g1s[(EE + e) * 16 + b] + db_hh1[EE + e]);
            float n  = tanh_fast(fmaf(r, db_hh1[2 * EE + e], g1s[(2 * EE + e) * 16 + b]));
            lastw[idx] = (1.0f - zg) * n;
        }
        __syncthreads();
        // pred[:, t, :] = lastword @ fc2^T + b
        if (tid < 256) {
            int b = tid >> 4, kk0 = (tid & 15) * 4;
            float4 acc = *(const float4*)(fc2_b + kk0);
            #pragma unroll 5
            for (int e = 0; e < EE; e++) {
                float a = lastw[e * 16 + b];
                float4 wv = *(const float4*)(f2t + e * KV + kk0);
                acc.x = fmaf(wv.x, a, acc.x);
                acc.y = fmaf(wv.y, a, acc.y);
                acc.z = fmaf(wv.z, a, acc.z);
                acc.w = fmaf(wv.w, a, acc.w);
            }
            *(float4*)(out + PRED_OFF + ((size_t)(bg0 + b) * TT + t) * KV + kk0) = acc;
        }
        __syncthreads();
    }
}

extern "C" void kernel_launch(void* const* d_in, const int* in_sizes, int n_in,
                              void* d_out, int out_size) {
    (void)in_sizes; (void)n_in; (void)out_size;
    const int*   x       = (const int*)  d_in[0];
    const float* emb     = (const float*)d_in[1];
    const float* eW_ih0  = (const float*)d_in[2];
    const float* eW_hh0  = (const float*)d_in[3];
    const float* eb_ih0  = (const float*)d_in[4];
    const float* eb_hh0  = (const float*)d_in[5];
    const float* eW_ih1  = (const float*)d_in[6];
    const float* eW_hh1  = (const float*)d_in[7];
    const float* eb_ih1  = (const float*)d_in[8];
    const float* eb_hh1  = (const float*)d_in[9];
    const float* dW_ih0  = (const float*)d_in[10];
    const float* db_ih0  = (const float*)d_in[12];
    const float* db_hh0  = (const float*)d_in[13];
    const float* dW_ih1  = (const float*)d_in[14];
    const float* db_ih1  = (const float*)d_in[16];
    const float* db_hh1  = (const float*)d_in[17];
    const float* fc11_w  = (const float*)d_in[18];
    const float* fc11_b  = (const float*)d_in[19];
    const float* fc12_w  = (const float*)d_in[20];
    const float* fc12_b  = (const float*)d_in[21];
    const float* p1_w    = (const float*)d_in[22];
    const float* p1_b    = (const float*)d_in[23];
    const float* p2_w    = (const float*)d_in[24];
    const float* p2_b    = (const float*)d_in[25];
    const float* fc2_w   = (const float*)d_in[26];
    const float* fc2_b   = (const float*)d_in[27];
    const float* eps     = (const float*)d_in[28];

    {
        int maxtot = NTILES * NPH * 32;  // 16800
        dim3 grid((maxtot + 255) / 256, 4);
        pack_b16<<<grid, 256>>>(eW_ih0, eW_hh0, eW_ih1, eW_hh1);
    }

    cudaFuncSetAttribute((const void*)vae_all,
                         cudaFuncAttributeMaxDynamicSharedMemorySize,
                         SMEM_FLOATS * (int)sizeof(float));

    vae_all<<<NCTA, NTH, SMEM_FLOATS * sizeof(float)>>>(
        x, emb, eb_ih0, eb_hh0, eb_ih1, eb_hh1,
        dW_ih0, db_ih0, db_hh0, dW_ih1, db_ih1, db_hh1,
        fc11_w, fc11_b, fc12_w, fc12_b, p1_w, p1_b, p2_w, p2_b,
        fc2_w, fc2_b, eps, (float*)d_out);
}

// round 14
// speedup vs baseline: 3.1337x; 3.1337x over previous
#include <cuda_runtime.h>
#include <cuda_fp16.h>
#include <math.h>
#include <stdint.h>

// Problem dims
#define NB 4096
#define TT 128
#define KV 64
#define EE 35
#define LL 200
#define GE3 105
#define LE 235

#define NTH 800    // 25 warps
#define BBLK 32
#define NCTA (NB / BBLK)   // 128

// fp16 m16n8k16, k16-PAIR packed B: ih0 K=35 -> 2 pairs; hh K=200 -> 7 pairs
#define NP0 2
#define NPH 7
#define NTILES 75

// Output layout: concat(pred[B,T,K], mu[B,L], logvar[B,L], predY[B,1])
#define PRED_OFF ((size_t)0)
#define MU_OFF   ((size_t)NB * TT * KV)
#define LV_OFF   (MU_OFF + (size_t)NB * LL)
#define PY_OFF   (LV_OFF + (size_t)NB * LL)

__device__ uint4 g_b0ih[NTILES * NP0 * 32];
__device__ uint4 g_b0hh[NTILES * NPH * 32];
__device__ uint4 g_b1ih[NTILES * NPH * 32];
__device__ uint4 g_b1hh[NTILES * NPH * 32];

// SMEM layout (floats) — exact R12 arrangement (proven 2934us)
#define HPAD 36
#define OFF_EMB 0        // 2240
#define OFF_CB  2240     // 1600
#define OFF_H1  3840     // 7200 (UNUSED during encoder now; kept for overlay map)
#define OFF_H2  11040    // 7200
#define OFF_AXE 18240    // 1536 (4 k16 x 32 x 12)
#define OFF_AH1 19776    // 5376 (14 x 32 x 12)
#define OFF_AH2 25152    // 5376
#define OFF_TOK 30528    // 4096
#define SMEM_FLOATS 34624
// ---- post-encoder overlays (regions dead at time of use) ----
#define OFF_MUS 0        // 6400
#define OFF_W0  0        // 3675 dW_ih0[:,L:]
#define OFF_W1  3680     // 3675 dW_ih1
#define OFF_F2T 7360     // 2240 fc2^T [35][64]
#define OFF_T1  11040    // 6400 (over h2s)
#define OFF_ZS  18240    // 6400 (over axe+ah1)
#define OFF_GZ  25152    // 3360 (over ah2)
#define OFF_G1  28512    // 3360
#define OFF_HD  31872    // 1120
#define OFF_LW  32992    // 1120

// Fast transcendentals (MUFU-based): rel err ~1e-6, below fp16-mma noise.
__device__ __forceinline__ float sigm(float v) {
    return __fdividef(1.0f, 1.0f + __expf(-v));
}
__device__ __forceinline__ float tanh_fast(float x) {
    float e = __expf(2.0f * x);
    return fmaf(-2.0f, __fdividef(1.0f, e + 1.0f), 1.0f);
}

__device__ __forceinline__ void mma16(float (&c)[4], const uint32_t (&a)[4], uint2 b) {
    asm volatile(
        "mma.sync.aligned.m16n8k16.row.col.f32.f16.f16.f32 "
        "{%0,%1,%2,%3}, {%4,%5,%6,%7}, {%8,%9}, {%0,%1,%2,%3};"
        : "+f"(c[0]), "+f"(c[1]), "+f"(c[2]), "+f"(c[3])
        : "r"(a[0]), "r"(a[1]), "r"(a[2]), "r"(a[3]), "r"(b.x), "r"(b.y));
}

__device__ __forceinline__ uint32_t h2bits(float lo, float hi) {
    __half2 h = __floats2half2_rn(lo, hi);
    return *(uint32_t*)&h;
}

// ---- prep: pack weights into paired-k16 fp16 B-fragment layout ----
__global__ void pack_b16(const float* __restrict__ s0, const float* __restrict__ s1,
                         const float* __restrict__ s2, const float* __restrict__ s3) {
    int m = blockIdx.y;
    const float* src = (m == 0) ? s0 : (m == 1) ? s1 : (m == 2) ? s2 : s3;
    uint4* dst = (m == 0) ? g_b0ih : (m == 1) ? g_b0hh : (m == 2) ? g_b1ih : g_b1hh;
    int K  = (m == 0) ? EE : LL;
    int np = (m == 0) ? NP0 : NPH;
    int idx = blockIdx.x * blockDim.x + threadIdx.x;
    int total = NTILES * np * 32;
    if (idx >= total) return;
    int lane = idx & 31;
    int r = idx >> 5;
    int kp = r % np;  r /= np;
    int tile = r;
    int gid = lane >> 2, tig = lane & 3;
    int n = tile * 8 + gid;
    float w[8];
    #pragma unroll
    for (int half = 0; half < 2; half++) {
        int kA = (2 * kp + half) * 16 + 2 * tig;
        w[half * 4 + 0] = (kA     < K) ? src[n * K + kA]     : 0.0f;
        w[half * 4 + 1] = (kA + 1 < K) ? src[n * K + kA + 1] : 0.0f;
        w[half * 4 + 2] = (kA + 8 < K) ? src[n * K + kA + 8] : 0.0f;
        w[half * 4 + 3] = (kA + 9 < K) ? src[n * K + kA + 9] : 0.0f;
    }
    dst[idx] = make_uint4(h2bits(w[0], w[1]), h2bits(w[2], w[3]),
                          h2bits(w[4], w[5]), h2bits(w[6], w[7]));
}

// MMA pass (R8/R12-proven form)
__device__ __forceinline__ void enc_pass(const uint32_t* __restrict__ atfA,
                                         const uint4* __restrict__ B, int np,
                                         float (&cr)[2][4], float (&cz)[2][4], float (&cn)[2][4],
                                         int wrp, int lane)
{
    const uint4* pr = B + (size_t)(wrp * np) * 32 + lane;
    const uint4* pz = pr + (size_t)25 * np * 32;
    const uint4* pn = pz + (size_t)25 * np * 32;
    #pragma unroll 1
    for (int kp = 0; kp < np; kp++) {
        uint4 br = pr[kp * 32];
        uint4 bz = pz[kp * 32];
        uint4 bn = pn[kp * 32];
        const uint32_t* p0 = atfA + ((2 * kp) * 32 + lane) * 12;
        const uint32_t* p1 = p0 + 32 * 12;
        uint4 v00 = *(const uint4*)p0;
        uint4 v01 = *(const uint4*)(p0 + 4);
        uint4 v10 = *(const uint4*)p1;
        uint4 v11 = *(const uint4*)(p1 + 4);
        uint32_t ae0[4] = {v00.x, v00.y, v00.z, v00.w};
        uint32_t ae1[4] = {v01.x, v01.y, v01.z, v01.w};
        uint32_t ao0[4] = {v10.x, v10.y, v10.z, v10.w};
        uint32_t ao1[4] = {v11.x, v11.y, v11.z, v11.w};
        uint2 bre = make_uint2(br.x, br.y), bro = make_uint2(br.z, br.w);
        uint2 bze = make_uint2(bz.x, bz.y), bzo = make_uint2(bz.z, bz.w);
        uint2 bne = make_uint2(bn.x, bn.y), bno = make_uint2(bn.z, bn.w);
        mma16(cr[0], ae0, bre);  mma16(cr[1], ae1, bre);
        mma16(cz[0], ae0, bze);  mma16(cz[1], ae1, bze);
        mma16(cn[0], ae0, bne);  mma16(cn[1], ae1, bne);
        mma16(cr[0], ao0, bro);  mma16(cr[1], ao1, bro);
        mma16(cz[0], ao0, bzo);  mma16(cz[1], ao1, bzo);
        mma16(cn[0], ao0, bno);  mma16(cn[1], ao1, bno);
    }
}

// Layer-0 GRU epilogue: hidden state entirely IN REGISTERS (hp[8]).
// Same math order as the SMEM version -> bitwise-identical results.
__device__ __forceinline__ void gru_epi_reg(float (&hp)[8], uint32_t* __restrict__ atf_dst,
                                            const float* __restrict__ cb,
                                            float (&cr)[2][4], float (&cz)[2][4],
                                            float (&ci)[2][4], float (&ch)[2][4],
                                            int wrp, int lane)
{
    int tig = lane & 3;
    int j0 = 8 * wrp + 2 * tig;
    int k16d = wrp >> 1, khalf = wrp & 1;
    uint32_t* dst = atf_dst + (k16d * 32 + lane) * 12 + khalf * 2;
    float br0 = cb[j0], br1 = cb[j0 + 1];
    float bz0 = cb[200 + j0], bz1 = cb[200 + j0 + 1];
    float bi0 = cb[400 + j0], bi1 = cb[400 + j0 + 1];
    float bh0 = cb[600 + j0], bh1 = cb[600 + j0 + 1];
    #pragma unroll
    for (int m = 0; m < 2; m++) {
        uint32_t w[2];
        #pragma unroll
        for (int bh = 0; bh < 2; bh++) {
            float hv[2];
            #pragma unroll
            for (int d = 0; d < 2; d++) {
                int i = bh * 2 + d;
                int s = m * 4 + bh * 2 + d;
                float r = sigm(cr[m][i] + (d ? br1 : br0));
                float z = sigm(cz[m][i] + (d ? bz1 : bz0));
                float n = tanh_fast(ci[m][i] + (d ? bi1 : bi0) + r * (ch[m][i] + (d ? bh1 : bh0)));
                float ho = hp[s];
                float hn = n + z * (ho - n);
                hp[s] = hn;
                hv[d] = hn;
            }
            w[bh] = h2bits(hv[0], hv[1]);
        }
        *(uint2*)(dst + m * 4) = make_uint2(w[0], w[1]);
    }
}

// Layer-1 GRU epilogue: h2 in SMEM (heads read it later). R12-proven.
__device__ __forceinline__ void gru_epi(float* __restrict__ hb, uint32_t* __restrict__ atf_dst,
                                        const float* __restrict__ cb,
                                        float (&cr)[2][4], float (&cz)[2][4],
                                        float (&ci)[2][4], float (&ch)[2][4],
                                        int wrp, int lane)
{
    int gid = lane >> 2, tig = lane & 3;
    int j0 = 8 * wrp + 2 * tig;
    int k16d = wrp >> 1, khalf = wrp & 1;
    uint32_t* dst = atf_dst + (k16d * 32 + lane) * 12 + khalf * 2;
    float br0 = cb[j0], br1 = cb[j0 + 1];
    float bz0 = cb[200 + j0], bz1 = cb[200 + j0 + 1];
    float bi0 = cb[400 + j0], bi1 = cb[400 + j0 + 1];
    float bh0 = cb[600 + j0], bh1 = cb[600 + j0 + 1];
    #pragma unroll
    for (int m = 0; m < 2; m++) {
        uint32_t w[2];
        #pragma unroll
        for (int bh = 0; bh < 2; bh++) {
            int b = m * 16 + bh * 8 + gid;
            float hv[2];
            #pragma unroll
            for (int d = 0; d < 2; d++) {
                int i = bh * 2 + d;
                int j = j0 + d;
                float r = sigm(cr[m][i] + (d ? br1 : br0));
                float z = sigm(cz[m][i] + (d ? bz1 : bz0));
                float n = tanh_fast(ci[m][i] + (d ? bi1 : bi0) + r * (ch[m][i] + (d ? bh1 : bh0)));
                float ho = hb[j * HPAD + b];
                float hn = n + z * (ho - n);
                hb[j * HPAD + b] = hn;
                hv[d] = hn;
            }
            w[bh] = h2bits(hv[0], hv[1]);
        }
        *(uint2*)(dst + m * 4) = make_uint2(w[0], w[1]);
    }
}

extern "C" __global__ void __launch_bounds__(NTH, 1)
vae_all(const int* __restrict__ x, const float* __restrict__ emb,
        const float* __restrict__ eb_ih0, const float* __restrict__ eb_hh0,
        const float* __restrict__ eb_ih1, const float* __restrict__ eb_hh1,
        const float* __restrict__ dW_ih0, const float* __restrict__ db_ih0,
        const float* __restrict__ db_hh0,
        const float* __restrict__ dW_ih1, const float* __restrict__ db_ih1,
        const float* __restrict__ db_hh1,
        const float* __restrict__ fc11_w, const float* __restrict__ fc11_b,
        const float* __restrict__ fc12_w, const float* __restrict__ fc12_b,
        const float* __restrict__ p1_w,  const float* __restrict__ p1_b,
        const float* __restrict__ p2_w,  const float* __restrict__ p2_b,
        const float* __restrict__ fc2_w, const float* __restrict__ fc2_b,
        const float* __restrict__ eps,   float* __restrict__ out)
{
    extern __shared__ float sm[];
    float* emb_s = sm + OFF_EMB;
    float* cb_s  = sm + OFF_CB;
    float* h2s   = sm + OFF_H2;
    uint32_t* axe = (uint32_t*)(sm + OFF_AXE);
    uint32_t* ah1 = (uint32_t*)(sm + OFF_AH1);
    uint32_t* ah2 = (uint32_t*)(sm + OFF_AH2);
    int* toks = (int*)(sm + OFF_TOK);

    const int tid = threadIdx.x;
    const int bg0 = blockIdx.x * BBLK;

    for (int i = tid; i < KV * EE; i += NTH) emb_s[i] = emb[i];
    for (int i = tid; i < 200 * HPAD; i += NTH) h2s[i] = 0.0f;
    for (int i = tid; i < 4 * 32 * 12; i += NTH) axe[i] = 0u;
    for (int i = tid; i < 14 * 32 * 12; i += NTH) { ah1[i] = 0u; ah2[i] = 0u; }
    for (int i = tid; i < TT * 32; i += NTH) {
        int t = i >> 5, b = i & 31;
        toks[i] = x[(size_t)(bg0 + b) * TT + t];
    }
    for (int i = tid; i < 1600; i += NTH) {
        int l = i / 800, rem = i % 800, g = rem / 200, j = rem % 200;
        const float* bi = l ? eb_ih1 : eb_ih0;
        const float* bh = l ? eb_hh1 : eb_hh0;
        float v;
        if      (g == 0) v = bi[j] + bh[j];
        else if (g == 1) v = bi[200 + j] + bh[200 + j];
        else if (g == 2) v = bi[400 + j];
        else             v = bh[400 + j];
        cb_s[i] = v;
    }
    __syncthreads();

    const int lane = tid & 31;
    const int wrp  = tid >> 5;

    const int jt = tid >> 3;
    const int j0e = jt * 2;
    const int b0e = (tid & 7) * 4;

    // layer-0 hidden state in registers (per-thread fixed coords), init 0
    float h1reg[8] = {0, 0, 0, 0, 0, 0, 0, 0};

    // =====================  ENCODER (fp16 mma, paired-k16 B)  =====================
    for (int t = 0; t < TT; t++) {
        if (tid < 576) {
            int kp = tid >> 5, b = tid & 31;
            int k = kp * 2;
            int tok = toks[t * 32 + b];
            float e0 = emb_s[tok * EE + k];
            float e1 = (k + 1 < EE) ? emb_s[tok * EE + k + 1] : 0.0f;
            int jj = k & 15, k16 = k >> 4;
            int tigp = (jj & 7) >> 1, khalf = jj >> 3;
            int mhalf = (b >> 3) & 1, mt = b >> 4, gidp = b & 7;
            axe[(k16 * 32 + gidp * 4 + tigp) * 12 + mt * 4 + khalf * 2 + mhalf] = h2bits(e0, e1);
        }
        __syncthreads();

        {   // ---- layer 0 (h1 in registers) ----
            float cr[2][4] = {}, cz[2][4] = {}, ci[2][4] = {}, ch[2][4] = {};
            enc_pass(axe, g_b0ih, NP0, cr, cz, ci, wrp, lane);
            enc_pass(ah1, g_b0hh, NPH, cr, cz, ch, wrp, lane);
            __syncthreads();
            gru_epi_reg(h1reg, ah1, cb_s, cr, cz, ci, ch, wrp, lane);
        }
        __syncthreads();
        {   // ---- layer 1 (h2 in SMEM for heads) ----
            float cr[2][4] = {}, cz[2][4] = {}, ci[2][4] = {}, ch[2][4] = {};
            enc_pass(ah1, g_b1ih, NPH, cr, cz, ci, wrp, lane);
            enc_pass(ah2, g_b1hh, NPH, cr, cz, ch, wrp, lane);
            __syncthreads();
            gru_epi(h2s, ah2, cb_s + 800, cr, cz, ci, ch, wrp, lane);
        }
        __syncthreads();
    }

    float* mus   = sm + OFF_MUS;
    float* t1s   = sm + OFF_T1;
    float* zs    = sm + OFF_ZS;
    float* gzs   = sm + OFF_GZ;
    float* g1s   = sm + OFF_G1;
    float* hds   = sm + OFF_HD;
    float* lastw = sm + OFF_LW;
    float* w0s   = sm + OFF_W0;
    float* w1s   = sm + OFF_W1;
    float* f2t   = sm + OFF_F2T;

    // =====================  HEADS  =====================
    {
        float am[2][4], al[2][4];
        #pragma unroll
        for (int jj = 0; jj < 2; jj++) {
            float bm = fc11_b[j0e + jj], bl = fc12_b[j0e + jj];
            #pragma unroll
            for (int b = 0; b < 4; b++) { am[jj][b] = bm; al[jj][b] = bl; }
        }
        const float* w1 = fc11_w + j0e * LL;
        const float* w2 = fc12_w + j0e * LL;
        #pragma unroll 1
        for (int k = 0; k < LL; k += 2) {
            float4 u = *(const float4*)(h2s + k * HPAD + b0e);
            float4 w = *(const float4*)(h2s + (k + 1) * HPAD + b0e);
            float va[4] = {u.x, u.y, u.z, u.w};
            float vb[4] = {w.x, w.y, w.z, w.w};
            #pragma unroll
            for (int jj = 0; jj < 2; jj++) {
                float2 a = *(const float2*)(w1 + jj * LL + k);
                float2 c = *(const float2*)(w2 + jj * LL + k);
                #pragma unroll
                for (int b = 0; b < 4; b++) {
                    am[jj][b] = fmaf(a.x, va[b], am[jj][b]);
                    am[jj][b] = fmaf(a.y, vb[b], am[jj][b]);
                    al[jj][b] = fmaf(c.x, va[b], al[jj][b]);
                    al[jj][b] = fmaf(c.y, vb[b], al[jj][b]);
                }
            }
        }
        __syncthreads();   // h2s reads done before overlays
        #pragma unroll
        for (int jj = 0; jj < 2; jj++)
            #pragma unroll
            for (int b = 0; b < 4; b++) {
                int j = j0e + jj, bb = b0e + b, bg = bg0 + bb;
                float m = am[jj][b], lv = al[jj][b];
                out[MU_OFF + (size_t)bg * LL + j] = m;
                out[LV_OFF + (size_t)bg * LL + j] = lv;
                mus[j * 32 + bb] = m;
                zs[j * 32 + bb] = fmaf(eps[(size_t)bg * LL + j], expf(0.5f * lv), m);
            }
        __syncthreads();
    }
    {   // t1 = relu(mu @ p1^T + b)
        float aa[2][4];
        #pragma unroll
        for (int jj = 0; jj < 2; jj++) {
            float bv = p1_b[j0e + jj];
            #pragma unroll
            for (int b = 0; b < 4; b++) aa[jj][b] = bv;
        }
        const float* w1 = p1_w + j0e * LL;
        #pragma unroll 1
        for (int k = 0; k < LL; k += 2) {
            float4 u = *(const float4*)(mus + k * 32 + b0e);
            float4 w = *(const float4*)(mus + (k + 1) * 32 + b0e);
            float va[4] = {u.x, u.y, u.z, u.w};
            float vb[4] = {w.x, w.y, w.z, w.w};
            #pragma unroll
            for (int jj = 0; jj < 2; jj++) {
                float2 a = *(const float2*)(w1 + jj * LL + k);
                #pragma unroll
                for (int b = 0; b < 4; b++) {
                    aa[jj][b] = fmaf(a.x, va[b], aa[jj][b]);
                    aa[jj][b] = fmaf(a.y, vb[b], aa[jj][b]);
                }
            }
        }
        #pragma unroll
        for (int jj = 0; jj < 2; jj++)
            #pragma unroll
            for (int b = 0; b < 4; b++)
                t1s[(j0e + jj) * 32 + b0e + b] = fmaxf(aa[jj][b], 0.0f);
        __syncthreads();   // mus reads done; t1s visible
    }
    if (tid < 32) {
        float a = p2_b[0];
        for (int j = 0; j < LL; j++) a = fmaf(p2_w[j], t1s[j * 32 + tid], a);
        out[PY_OFF + bg0 + tid] = a;
    }
    for (int idx = tid; idx < GE3 * 32; idx += NTH) {
        int g = idx >> 5, b = idx & 31;
        float a = db_ih0[g];
        const float* w = dW_ih0 + g * LE;
        #pragma unroll 4
        for (int k = 0; k < LL; k++) a = fmaf(zs[k * 32 + b], w[k], a);
        gzs[idx] = a;
    }
    for (int i = tid; i < GE3 * EE; i += NTH) {
        w0s[i] = dW_ih0[(i / EE) * LE + LL + (i % EE)];
        w1s[i] = dW_ih1[i];
    }
    for (int i = tid; i < EE * KV; i += NTH)
        f2t[i] = fc2_w[(i & 63) * EE + (i >> 6)];
    for (int i = tid; i < EE * 32; i += NTH) lastw[i] = 0.0f;
    __syncthreads();

    // =====================  DECODER (fp32 SIMT, vectorized x4)  =====================
    for (int t = 0; t < TT; t++) {
        for (int idx = tid; idx < GE3 * 8; idx += NTH) {
            int g = idx >> 3, b0 = (idx & 7) * 4;
            float4 acc = *(const float4*)(gzs + g * 32 + b0);
            const float* w = w0s + g * EE;
            #pragma unroll 5
            for (int k = 0; k < EE; k++) {
                float4 a = *(const float4*)(lastw + k * 32 + b0);
                float wv = w[k];
                acc.x = fmaf(wv, a.x, acc.x);
                acc.y = fmaf(wv, a.y, acc.y);
                acc.z = fmaf(wv, a.z, acc.z);
                acc.w = fmaf(wv, a.w, acc.w);
            }
            *(float4*)(g1s + g * 32 + b0) = acc;
        }
        __syncthreads();
        for (int idx = tid; idx < EE * 32; idx += NTH) {
            int e = idx >> 5, b = idx & 31;
            float r  = sigm(g1s[e * 32 + b] + db_hh0[e]);
            float zg = sigm(g1s[(EE + e) * 32 + b] + db_hh0[EE + e]);
            float n  = tanh_fast(fmaf(r, db_hh0[2 * EE + e], g1s[(2 * EE + e) * 32 + b]));
            hds[idx] = (1.0f - zg) * n;
        }
        __syncthreads();
        for (int idx = tid; idx < GE3 * 8; idx += NTH) {
            int g = idx >> 3, b0 = (idx & 7) * 4;
            float bv = db_ih1[g];
            float4 acc = make_float4(bv, bv, bv, bv);
            const float* w = w1s + g * EE;
            #pragma unroll 5
            for (int k = 0; k < EE; k++) {
                float4 a = *(const float4*)(hds + k * 32 + b0);
                float wv = w[k];
                acc.x = fmaf(wv, a.x, acc.x);
                acc.y = fmaf(wv, a.y, acc.y);
                acc.z = fmaf(wv, a.z, acc.z);
                acc.w = fmaf(wv, a.w, acc.w);
            }
            *(float4*)(g1s + g * 32 + b0) = acc;
        }
        __syncthreads();
        for (int idx = tid; idx < EE * 32; idx += NTH) {
            int e = idx >> 5, b = idx & 31;
            float r  = sigm(g1s[e * 32 + b] + db_hh1[e]);
            float zg = sigm(g1s[(EE + e) * 32 + b] + db_hh1[EE + e]);
            float n  = tanh_fast(fmaf(r, db_hh1[2 * EE + e], g1s[(2 * EE + e) * 32 + b]));
            lastw[idx] = (1.0f - zg) * n;
        }
        __syncthreads();
        // pred[:, t, :] = lastword @ fc2^T + b
        if (tid < 512) {
            int b = tid >> 4, kk0 = (tid & 15) * 4;
            float4 acc = *(const float4*)(fc2_b + kk0);
            #pragma unroll 5
            for (int e = 0; e < EE; e++) {
                float a = lastw[e * 32 + b];
                float4 wv = *(const float4*)(f2t + e * KV + kk0);
                acc.x = fmaf(wv.x, a, acc.x);
                acc.y = fmaf(wv.y, a, acc.y);
                acc.z = fmaf(wv.z, a, acc.z);
                acc.w = fmaf(wv.w, a, acc.w);
            }
            *(float4*)(out + PRED_OFF + ((size_t)(bg0 + b) * TT + t) * KV + kk0) = acc;
        }
        __syncthreads();
    }
}

extern "C" void kernel_launch(void* const* d_in, const int* in_sizes, int n_in,
                              void* d_out, int out_size) {
    (void)in_sizes; (void)n_in; (void)out_size;
    const int*   x       = (const int*)  d_in[0];
    const float* emb     = (const float*)d_in[1];
    const float* eW_ih0  = (const float*)d_in[2];
    const float* eW_hh0  = (const float*)d_in[3];
    const float* eb_ih0  = (const float*)d_in[4];
    const float* eb_hh0  = (const float*)d_in[5];
    const float* eW_ih1  = (const float*)d_in[6];
    const float* eW_hh1  = (const float*)d_in[7];
    const float* eb_ih1  = (const float*)d_in[8];
    const float* eb_hh1  = (const float*)d_in[9];
    const float* dW_ih0  = (const float*)d_in[10];
    const float* db_ih0  = (const float*)d_in[12];
    const float* db_hh0  = (const float*)d_in[13];
    const float* dW_ih1  = (const float*)d_in[14];
    const float* db_ih1  = (const float*)d_in[16];
    const float* db_hh1  = (const float*)d_in[17];
    const float* fc11_w  = (const float*)d_in[18];
    const float* fc11_b  = (const float*)d_in[19];
    const float* fc12_w  = (const float*)d_in[20];
    const float* fc12_b  = (const float*)d_in[21];
    const float* p1_w    = (const float*)d_in[22];
    const float* p1_b    = (const float*)d_in[23];
    const float* p2_w    = (const float*)d_in[24];
    const float* p2_b    = (const float*)d_in[25];
    const float* fc2_w   = (const float*)d_in[26];
    const float* fc2_b   = (const float*)d_in[27];
    const float* eps     = (const float*)d_in[28];

    {
        int maxtot = NTILES * NPH * 32;  // 16800
        dim3 grid((maxtot + 255) / 256, 4);
        pack_b16<<<grid, 256>>>(eW_ih0, eW_hh0, eW_ih1, eW_hh1);
    }

    cudaFuncSetAttribute((const void*)vae_all,
                         cudaFuncAttributeMaxDynamicSharedMemorySize,
                         SMEM_FLOATS * (int)sizeof(float));

    vae_all<<<NCTA, NTH, SMEM_FLOATS * sizeof(float)>>>(
        x, emb, eb_ih0, eb_hh0, eb_ih1, eb_hh1,
        dW_ih0, db_ih0, db_hh0, dW_ih1, db_ih1, db_hh1,
        fc11_w, fc11_b, fc12_w, fc12_b, p1_w, p1_b, p2_w, p2_b,
        fc2_w, fc2_b, eps, (float*)d_out);
}

// round 15
// speedup vs baseline: 3.1734x; 1.0127x over previous
#include <cuda_runtime.h>
#include <cuda_fp16.h>
#include <math.h>
#include <stdint.h>

// Problem dims
#define NB 4096
#define TT 128
#define KV 64
#define EE 35
#define LL 200
#define GE3 105
#define LE 235

#define NTH 800    // 25 warps
#define BBLK 32
#define NCTA (NB / BBLK)   // 128

// fp16 m16n8k16, k16-PAIR packed B: ih0 K=35 -> 2 pairs; hh K=200 -> 7 pairs
#define NP0 2
#define NPH 7
#define NTILES 75

// Output layout: concat(pred[B,T,K], mu[B,L], logvar[B,L], predY[B,1])
#define PRED_OFF ((size_t)0)
#define MU_OFF   ((size_t)NB * TT * KV)
#define LV_OFF   (MU_OFF + (size_t)NB * LL)
#define PY_OFF   (LV_OFF + (size_t)NB * LL)

__device__ uint4 g_b0ih[NTILES * NP0 * 32];
__device__ uint4 g_b0hh[NTILES * NPH * 32];
__device__ uint4 g_b1ih[NTILES * NPH * 32];
__device__ uint4 g_b1hh[NTILES * NPH * 32];

// SMEM layout (floats) — exact R12 arrangement (proven 2934us)
#define HPAD 36
#define OFF_EMB 0        // 2240
#define OFF_CB  2240     // 1600
#define OFF_H1  3840     // 7200 (200 x 36 fp32)
#define OFF_H2  11040    // 7200
#define OFF_AXE 18240    // 1536 (4 k16 x 32 x 12)
#define OFF_AH1 19776    // 5376 (14 x 32 x 12)
#define OFF_AH2 25152    // 5376
#define OFF_TOK 30528    // 4096
#define SMEM_FLOATS 34624
// ---- post-encoder overlays (regions dead at time of use) ----
#define OFF_MUS 0        // 6400
#define OFF_W0  0        // 3675 dW_ih0[:,L:]
#define OFF_W1  3680     // 3675 dW_ih1
#define OFF_F2T 7360     // 2240 fc2^T [35][64]
#define OFF_T1  11040    // 6400 (over h2s)
#define OFF_ZS  18240    // 6400 (over axe+ah1)
#define OFF_GZ  25152    // 3360 (over ah2)
#define OFF_G1  28512    // 3360
#define OFF_HD  31872    // 1120
#define OFF_LW  32992    // 1120

// Fast transcendentals (MUFU-based)
__device__ __forceinline__ float sigm(float v) {
    return __fdividef(1.0f, 1.0f + __expf(-v));
}
__device__ __forceinline__ float tanh_fast(float x) {
    float e = __expf(2.0f * x);
    return fmaf(-2.0f, __fdividef(1.0f, e + 1.0f), 1.0f);
}

__device__ __forceinline__ void mma16(float (&c)[4], const uint32_t (&a)[4], uint2 b) {
    asm volatile(
        "mma.sync.aligned.m16n8k16.row.col.f32.f16.f16.f32 "
        "{%0,%1,%2,%3}, {%4,%5,%6,%7}, {%8,%9}, {%0,%1,%2,%3};"
        : "+f"(c[0]), "+f"(c[1]), "+f"(c[2]), "+f"(c[3])
        : "r"(a[0]), "r"(a[1]), "r"(a[2]), "r"(a[3]), "r"(b.x), "r"(b.y));
}

__device__ __forceinline__ uint32_t h2bits(float lo, float hi) {
    __half2 h = __floats2half2_rn(lo, hi);
    return *(uint32_t*)&h;
}

// ---- prep: pack weights into paired-k16 fp16 B-fragment layout ----
__global__ void pack_b16(const float* __restrict__ s0, const float* __restrict__ s1,
                         const float* __restrict__ s2, const float* __restrict__ s3) {
    int m = blockIdx.y;
    const float* src = (m == 0) ? s0 : (m == 1) ? s1 : (m == 2) ? s2 : s3;
    uint4* dst = (m == 0) ? g_b0ih : (m == 1) ? g_b0hh : (m == 2) ? g_b1ih : g_b1hh;
    int K  = (m == 0) ? EE : LL;
    int np = (m == 0) ? NP0 : NPH;
    int idx = blockIdx.x * blockDim.x + threadIdx.x;
    int total = NTILES * np * 32;
    if (idx >= total) return;
    int lane = idx & 31;
    int r = idx >> 5;
    int kp = r % np;  r /= np;
    int tile = r;
    int gid = lane >> 2, tig = lane & 3;
    int n = tile * 8 + gid;
    float w[8];
    #pragma unroll
    for (int half = 0; half < 2; half++) {
        int kA = (2 * kp + half) * 16 + 2 * tig;
        w[half * 4 + 0] = (kA     < K) ? src[n * K + kA]     : 0.0f;
        w[half * 4 + 1] = (kA + 1 < K) ? src[n * K + kA + 1] : 0.0f;
        w[half * 4 + 2] = (kA + 8 < K) ? src[n * K + kA + 8] : 0.0f;
        w[half * 4 + 3] = (kA + 9 < K) ? src[n * K + kA + 9] : 0.0f;
    }
    dst[idx] = make_uint4(h2bits(w[0], w[1]), h2bits(w[2], w[3]),
                          h2bits(w[4], w[5]), h2bits(w[6], w[7]));
}

// One kp worth of MMAs, given already-loaded B (br,bz,bn) and the A base ptr.
__device__ __forceinline__ void kp_mmas(const uint32_t* __restrict__ p0,
                                        uint4 br, uint4 bz, uint4 bn,
                                        float (&cr)[2][4], float (&cz)[2][4], float (&cn)[2][4])
{
    const uint32_t* p1 = p0 + 32 * 12;
    uint4 v00 = *(const uint4*)p0;
    uint4 v01 = *(const uint4*)(p0 + 4);
    uint4 v10 = *(const uint4*)p1;
    uint4 v11 = *(const uint4*)(p1 + 4);
    uint32_t ae0[4] = {v00.x, v00.y, v00.z, v00.w};
    uint32_t ae1[4] = {v01.x, v01.y, v01.z, v01.w};
    uint32_t ao0[4] = {v10.x, v10.y, v10.z, v10.w};
    uint32_t ao1[4] = {v11.x, v11.y, v11.z, v11.w};
    uint2 bre = make_uint2(br.x, br.y), bro = make_uint2(br.z, br.w);
    uint2 bze = make_uint2(bz.x, bz.y), bzo = make_uint2(bz.z, bz.w);
    uint2 bne = make_uint2(bn.x, bn.y), bno = make_uint2(bn.z, bn.w);
    mma16(cr[0], ae0, bre);  mma16(cr[1], ae1, bre);
    mma16(cz[0], ae0, bze);  mma16(cz[1], ae1, bze);
    mma16(cn[0], ae0, bne);  mma16(cn[1], ae1, bne);
    mma16(cr[0], ao0, bro);  mma16(cr[1], ao1, bro);
    mma16(cz[0], ao0, bzo);  mma16(cz[1], ao1, bzo);
    mma16(cn[0], ao0, bno);  mma16(cn[1], ao1, bno);
}

// MMA pass, PAIRED kp bodies: 6 B loads batched up-front (MLP=6), then 24 MMAs
// + 8 A-LDS of latency cover. MMA order identical to R12 -> bitwise-same output.
__device__ __forceinline__ void enc_pass(const uint32_t* __restrict__ atfA,
                                         const uint4* __restrict__ B, int np,
                                         float (&cr)[2][4], float (&cz)[2][4], float (&cn)[2][4],
                                         int wrp, int lane)
{
    const uint4* pr = B + (size_t)(wrp * np) * 32 + lane;
    const uint4* pz = pr + (size_t)25 * np * 32;
    const uint4* pn = pz + (size_t)25 * np * 32;
    int kp = 0;
    #pragma unroll 1
    for (; kp + 2 <= np; kp += 2) {
        uint4 br0 = pr[kp * 32];
        uint4 bz0 = pz[kp * 32];
        uint4 bn0 = pn[kp * 32];
        uint4 br1 = pr[kp * 32 + 32];
        uint4 bz1 = pz[kp * 32 + 32];
        uint4 bn1 = pn[kp * 32 + 32];
        kp_mmas(atfA + ((2 * kp) * 32 + lane) * 12,     br0, bz0, bn0, cr, cz, cn);
        kp_mmas(atfA + ((2 * kp + 2) * 32 + lane) * 12, br1, bz1, bn1, cr, cz, cn);
    }
    if (kp < np) {
        uint4 br = pr[kp * 32];
        uint4 bz = pz[kp * 32];
        uint4 bn = pn[kp * 32];
        kp_mmas(atfA + ((2 * kp) * 32 + lane) * 12, br, bz, bn, cr, cz, cn);
    }
}

// Register GRU epilogue (R12-proven)
__device__ __forceinline__ void gru_epi(float* __restrict__ hb, uint32_t* __restrict__ atf_dst,
                                        const float* __restrict__ cb,
                                        float (&cr)[2][4], float (&cz)[2][4],
                                        float (&ci)[2][4], float (&ch)[2][4],
                                        int wrp, int lane)
{
    int gid = lane >> 2, tig = lane & 3;
    int j0 = 8 * wrp + 2 * tig;
    int k16d = wrp >> 1, khalf = wrp & 1;
    uint32_t* dst = atf_dst + (k16d * 32 + lane) * 12 + khalf * 2;
    float br0 = cb[j0], br1 = cb[j0 + 1];
    float bz0 = cb[200 + j0], bz1 = cb[200 + j0 + 1];
    float bi0 = cb[400 + j0], bi1 = cb[400 + j0 + 1];
    float bh0 = cb[600 + j0], bh1 = cb[600 + j0 + 1];
    #pragma unroll
    for (int m = 0; m < 2; m++) {
        uint32_t w[2];
        #pragma unroll
        for (int bh = 0; bh < 2; bh++) {
            int b = m * 16 + bh * 8 + gid;
            float hv[2];
            #pragma unroll
            for (int d = 0; d < 2; d++) {
                int i = bh * 2 + d;
                int j = j0 + d;
                float r = sigm(cr[m][i] + (d ? br1 : br0));
                float z = sigm(cz[m][i] + (d ? bz1 : bz0));
                float n = tanh_fast(ci[m][i] + (d ? bi1 : bi0) + r * (ch[m][i] + (d ? bh1 : bh0)));
                float ho = hb[j * HPAD + b];
                float hn = n + z * (ho - n);
                hb[j * HPAD + b] = hn;
                hv[d] = hn;
            }
            w[bh] = h2bits(hv[0], hv[1]);
        }
        *(uint2*)(dst + m * 4) = make_uint2(w[0], w[1]);
    }
}

extern "C" __global__ void __launch_bounds__(NTH, 1)
vae_all(const int* __restrict__ x, const float* __restrict__ emb,
        const float* __restrict__ eb_ih0, const float* __restrict__ eb_hh0,
        const float* __restrict__ eb_ih1, const float* __restrict__ eb_hh1,
        const float* __restrict__ dW_ih0, const float* __restrict__ db_ih0,
        const float* __restrict__ db_hh0,
        const float* __restrict__ dW_ih1, const float* __restrict__ db_ih1,
        const float* __restrict__ db_hh1,
        const float* __restrict__ fc11_w, const float* __restrict__ fc11_b,
        const float* __restrict__ fc12_w, const float* __restrict__ fc12_b,
        const float* __restrict__ p1_w,  const float* __restrict__ p1_b,
        const float* __restrict__ p2_w,  const float* __restrict__ p2_b,
        const float* __restrict__ fc2_w, const float* __restrict__ fc2_b,
        const float* __restrict__ eps,   float* __restrict__ out)
{
    extern __shared__ float sm[];
    float* emb_s = sm + OFF_EMB;
    float* cb_s  = sm + OFF_CB;
    float* h1s   = sm + OFF_H1;
    float* h2s   = sm + OFF_H2;
    uint32_t* axe = (uint32_t*)(sm + OFF_AXE);
    uint32_t* ah1 = (uint32_t*)(sm + OFF_AH1);
    uint32_t* ah2 = (uint32_t*)(sm + OFF_AH2);
    int* toks = (int*)(sm + OFF_TOK);

    const int tid = threadIdx.x;
    const int bg0 = blockIdx.x * BBLK;

    for (int i = tid; i < KV * EE; i += NTH) emb_s[i] = emb[i];
    for (int i = tid; i < 200 * HPAD; i += NTH) { h1s[i] = 0.0f; h2s[i] = 0.0f; }
    for (int i = tid; i < 4 * 32 * 12; i += NTH) axe[i] = 0u;
    for (int i = tid; i < 14 * 32 * 12; i += NTH) { ah1[i] = 0u; ah2[i] = 0u; }
    for (int i = tid; i < TT * 32; i += NTH) {
        int t = i >> 5, b = i & 31;
        toks[i] = x[(size_t)(bg0 + b) * TT + t];
    }
    for (int i = tid; i < 1600; i += NTH) {
        int l = i / 800, rem = i % 800, g = rem / 200, j = rem % 200;
        const float* bi = l ? eb_ih1 : eb_ih0;
        const float* bh = l ? eb_hh1 : eb_hh0;
        float v;
        if      (g == 0) v = bi[j] + bh[j];
        else if (g == 1) v = bi[200 + j] + bh[200 + j];
        else if (g == 2) v = bi[400 + j];
        else             v = bh[400 + j];
        cb_s[i] = v;
    }
    __syncthreads();

    const int lane = tid & 31;
    const int wrp  = tid >> 5;

    const int jt = tid >> 3;
    const int j0e = jt * 2;
    const int b0e = (tid & 7) * 4;

    // =====================  ENCODER (fp16 mma, paired-kp bodies)  =====================
    for (int t = 0; t < TT; t++) {
        if (tid < 576) {
            int kp = tid >> 5, b = tid & 31;
            int k = kp * 2;
            int tok = toks[t * 32 + b];
            float e0 = emb_s[tok * EE + k];
            float e1 = (k + 1 < EE) ? emb_s[tok * EE + k + 1] : 0.0f;
            int jj = k & 15, k16 = k >> 4;
            int tigp = (jj & 7) >> 1, khalf = jj >> 3;
            int mhalf = (b >> 3) & 1, mt = b >> 4, gidp = b & 7;
            axe[(k16 * 32 + gidp * 4 + tigp) * 12 + mt * 4 + khalf * 2 + mhalf] = h2bits(e0, e1);
        }
        __syncthreads();

        {   // ---- layer 0 ----
            float cr[2][4] = {}, cz[2][4] = {}, ci[2][4] = {}, ch[2][4] = {};
            enc_pass(axe, g_b0ih, NP0, cr, cz, ci, wrp, lane);
            enc_pass(ah1, g_b0hh, NPH, cr, cz, ch, wrp, lane);
            __syncthreads();
            gru_epi(h1s, ah1, cb_s, cr, cz, ci, ch, wrp, lane);
        }
        __syncthreads();
        {   // ---- layer 1 ----
            float cr[2][4] = {}, cz[2][4] = {}, ci[2][4] = {}, ch[2][4] = {};
            enc_pass(ah1, g_b1ih, NPH, cr, cz, ci, wrp, lane);
            enc_pass(ah2, g_b1hh, NPH, cr, cz, ch, wrp, lane);
            __syncthreads();
            gru_epi(h2s, ah2, cb_s + 800, cr, cz, ci, ch, wrp, lane);
        }
        __syncthreads();
    }

    float* mus   = sm + OFF_MUS;
    float* t1s   = sm + OFF_T1;
    float* zs    = sm + OFF_ZS;
    float* gzs   = sm + OFF_GZ;
    float* g1s   = sm + OFF_G1;
    float* hds   = sm + OFF_HD;
    float* lastw = sm + OFF_LW;
    float* w0s   = sm + OFF_W0;
    float* w1s   = sm + OFF_W1;
    float* f2t   = sm + OFF_F2T;

    // =====================  HEADS  =====================
    {
        float am[2][4], al[2][4];
        #pragma unroll
        for (int jj = 0; jj < 2; jj++) {
            float bm = fc11_b[j0e + jj], bl = fc12_b[j0e + jj];
            #pragma unroll
            for (int b = 0; b < 4; b++) { am[jj][b] = bm; al[jj][b] = bl; }
        }
        const float* w1 = fc11_w + j0e * LL;
        const float* w2 = fc12_w + j0e * LL;
        #pragma unroll 1
        for (int k = 0; k < LL; k += 2) {
            float4 u = *(const float4*)(h2s + k * HPAD + b0e);
            float4 w = *(const float4*)(h2s + (k + 1) * HPAD + b0e);
            float va[4] = {u.x, u.y, u.z, u.w};
            float vb[4] = {w.x, w.y, w.z, w.w};
            #pragma unroll
            for (int jj = 0; jj < 2; jj++) {
                float2 a = *(const float2*)(w1 + jj * LL + k);
                float2 c = *(const float2*)(w2 + jj * LL + k);
                #pragma unroll
                for (int b = 0; b < 4; b++) {
                    am[jj][b] = fmaf(a.x, va[b], am[jj][b]);
                    am[jj][b] = fmaf(a.y, vb[b], am[jj][b]);
                    al[jj][b] = fmaf(c.x, va[b], al[jj][b]);
                    al[jj][b] = fmaf(c.y, vb[b], al[jj][b]);
                }
            }
        }
        __syncthreads();   // h2s reads done before overlays
        #pragma unroll
        for (int jj = 0; jj < 2; jj++)
            #pragma unroll
            for (int b = 0; b < 4; b++) {
                int j = j0e + jj, bb = b0e + b, bg = bg0 + bb;
                float m = am[jj][b], lv = al[jj][b];
                out[MU_OFF + (size_t)bg * LL + j] = m;
                out[LV_OFF + (size_t)bg * LL + j] = lv;
                mus[j * 32 + bb] = m;
                zs[j * 32 + bb] = fmaf(eps[(size_t)bg * LL + j], expf(0.5f * lv), m);
            }
        __syncthreads();
    }
    {   // t1 = relu(mu @ p1^T + b)
        float aa[2][4];
        #pragma unroll
        for (int jj = 0; jj < 2; jj++) {
            float bv = p1_b[j0e + jj];
            #pragma unroll
            for (int b = 0; b < 4; b++) aa[jj][b] = bv;
        }
        const float* w1 = p1_w + j0e * LL;
        #pragma unroll 1
        for (int k = 0; k < LL; k += 2) {
            float4 u = *(const float4*)(mus + k * 32 + b0e);
            float4 w = *(const float4*)(mus + (k + 1) * 32 + b0e);
            float va[4] = {u.x, u.y, u.z, u.w};
            float vb[4] = {w.x, w.y, w.z, w.w};
            #pragma unroll
            for (int jj = 0; jj < 2; jj++) {
                float2 a = *(const float2*)(w1 + jj * LL + k);
                #pragma unroll
                for (int b = 0; b < 4; b++) {
                    aa[jj][b] = fmaf(a.x, va[b], aa[jj][b]);
                    aa[jj][b] = fmaf(a.y, vb[b], aa[jj][b]);
                }
            }
        }
        #pragma unroll
        for (int jj = 0; jj < 2; jj++)
            #pragma unroll
            for (int b = 0; b < 4; b++)
                t1s[(j0e + jj) * 32 + b0e + b] = fmaxf(aa[jj][b], 0.0f);
        __syncthreads();   // mus reads done; t1s visible
    }
    if (tid < 32) {
        float a = p2_b[0];
        for (int j = 0; j < LL; j++) a = fmaf(p2_w[j], t1s[j * 32 + tid], a);
        out[PY_OFF + bg0 + tid] = a;
    }
    for (int idx = tid; idx < GE3 * 32; idx += NTH) {
        int g = idx >> 5, b = idx & 31;
        float a = db_ih0[g];
        const float* w = dW_ih0 + g * LE;
        #pragma unroll 4
        for (int k = 0; k < LL; k++) a = fmaf(zs[k * 32 + b], w[k], a);
        gzs[idx] = a;
    }
    for (int i = tid; i < GE3 * EE; i += NTH) {
        w0s[i] = dW_ih0[(i / EE) * LE + LL + (i % EE)];
        w1s[i] = dW_ih1[i];
    }
    for (int i = tid; i < EE * KV; i += NTH)
        f2t[i] = fc2_w[(i & 63) * EE + (i >> 6)];
    for (int i = tid; i < EE * 32; i += NTH) lastw[i] = 0.0f;
    __syncthreads();

    // =====================  DECODER (fp32 SIMT, vectorized x4)  =====================
    for (int t = 0; t < TT; t++) {
        for (int idx = tid; idx < GE3 * 8; idx += NTH) {
            int g = idx >> 3, b0 = (idx & 7) * 4;
            float4 acc = *(const float4*)(gzs + g * 32 + b0);
            const float* w = w0s + g * EE;
            #pragma unroll 5
            for (int k = 0; k < EE; k++) {
                float4 a = *(const float4*)(lastw + k * 32 + b0);
                float wv = w[k];
                acc.x = fmaf(wv, a.x, acc.x);
                acc.y = fmaf(wv, a.y, acc.y);
                acc.z = fmaf(wv, a.z, acc.z);
                acc.w = fmaf(wv, a.w, acc.w);
            }
            *(float4*)(g1s + g * 32 + b0) = acc;
        }
        __syncthreads();
        for (int idx = tid; idx < EE * 32; idx += NTH) {
            int e = idx >> 5, b = idx & 31;
            float r  = sigm(g1s[e * 32 + b] + db_hh0[e]);
            float zg = sigm(g1s[(EE + e) * 32 + b] + db_hh0[EE + e]);
            float n  = tanh_fast(fmaf(r, db_hh0[2 * EE + e], g1s[(2 * EE + e) * 32 + b]));
            hds[idx] = (1.0f - zg) * n;
        }
        __syncthreads();
        for (int idx = tid; idx < GE3 * 8; idx += NTH) {
            int g = idx >> 3, b0 = (idx & 7) * 4;
            float bv = db_ih1[g];
            float4 acc = make_float4(bv, bv, bv, bv);
            const float* w = w1s + g * EE;
            #pragma unroll 5
            for (int k = 0; k < EE; k++) {
                float4 a = *(const float4*)(hds + k * 32 + b0);
                float wv = w[k];
                acc.x = fmaf(wv, a.x, acc.x);
                acc.y = fmaf(wv, a.y, acc.y);
                acc.z = fmaf(wv, a.z, acc.z);
                acc.w = fmaf(wv, a.w, acc.w);
            }
            *(float4*)(g1s + g * 32 + b0) = acc;
        }
        __syncthreads();
        for (int idx = tid; idx < EE * 32; idx += NTH) {
            int e = idx >> 5, b = idx & 31;
            float r  = sigm(g1s[e * 32 + b] + db_hh1[e]);
            float zg = sigm(g1s[(EE + e) * 32 + b] + db_hh1[EE + e]);
            float n  = tanh_fast(fmaf(r, db_hh1[2 * EE + e], g1s[(2 * EE + e) * 32 + b]));
            lastw[idx] = (1.0f - zg) * n;
        }
        __syncthreads();
        // fc2 reads lastw/f2t only; next gi1 writes g1s whose prior readers were
        // ordered by the sync above -> no trailing barrier (R8-proven safe).
        if (tid < 512) {
            int b = tid >> 4, kk0 = (tid & 15) * 4;
            float4 acc = *(const float4*)(fc2_b + kk0);
            #pragma unroll 5
            for (int e = 0; e < EE; e++) {
                float a = lastw[e * 32 + b];
                float4 wv = *(const float4*)(f2t + e * KV + kk0);
                acc.x = fmaf(wv.x, a, acc.x);
                acc.y = fmaf(wv.y, a, acc.y);
                acc.z = fmaf(wv.z, a, acc.z);
                acc.w = fmaf(wv.w, a, acc.w);
            }
            *(float4*)(out + PRED_OFF + ((size_t)(bg0 + b) * TT + t) * KV + kk0) = acc;
        }
    }
}

extern "C" void kernel_launch(void* const* d_in, const int* in_sizes, int n_in,
                              void* d_out, int out_size) {
    (void)in_sizes; (void)n_in; (void)out_size;
    const int*   x       = (const int*)  d_in[0];
    const float* emb     = (const float*)d_in[1];
    const float* eW_ih0  = (const float*)d_in[2];
    const float* eW_hh0  = (const float*)d_in[3];
    const float* eb_ih0  = (const float*)d_in[4];
    const float* eb_hh0  = (const float*)d_in[5];
    const float* eW_ih1  = (const float*)d_in[6];
    const float* eW_hh1  = (const float*)d_in[7];
    const float* eb_ih1  = (const float*)d_in[8];
    const float* eb_hh1  = (const float*)d_in[9];
    const float* dW_ih0  = (const float*)d_in[10];
    const float* db_ih0  = (const float*)d_in[12];
    const float* db_hh0  = (const float*)d_in[13];
    const float* dW_ih1  = (const float*)d_in[14];
    const float* db_ih1  = (const float*)d_in[16];
    const float* db_hh1  = (const float*)d_in[17];
    const float* fc11_w  = (const float*)d_in[18];
    const float* fc11_b  = (const float*)d_in[19];
    const float* fc12_w  = (const float*)d_in[20];
    const float* fc12_b  = (const float*)d_in[21];
    const float* p1_w    = (const float*)d_in[22];
    const float* p1_b    = (const float*)d_in[23];
    const float* p2_w    = (const float*)d_in[24];
    const float* p2_b    = (const float*)d_in[25];
    const float* fc2_w   = (const float*)d_in[26];
    const float* fc2_b   = (const float*)d_in[27];
    const float* eps     = (const float*)d_in[28];

    {
        int maxtot = NTILES * NPH * 32;  // 16800
        dim3 grid((maxtot + 255) / 256, 4);
        pack_b16<<<grid, 256>>>(eW_ih0, eW_hh0, eW_ih1, eW_hh1);
    }

    cudaFuncSetAttribute((const void*)vae_all,
                         cudaFuncAttributeMaxDynamicSharedMemorySize,
                         SMEM_FLOATS * (int)sizeof(float));

    vae_all<<<NCTA, NTH, SMEM_FLOATS * sizeof(float)>>>(
        x, emb, eb_ih0, eb_hh0, eb_ih1, eb_hh1,
        dW_ih0, db_ih0, db_hh0, dW_ih1, db_ih1, db_hh1,
        fc11_w, fc11_b, fc12_w, fc12_b, p1_w, p1_b, p2_w, p2_b,
        fc2_w, fc2_b, eps, (float*)d_out);
}

// round 16
// speedup vs baseline: 3.2829x; 1.0345x over previous
#include <cuda_runtime.h>
#include <cuda_fp16.h>
#include <math.h>
#include <stdint.h>

// Problem dims
#define NB 4096
#define TT 128
#define KV 64
#define EE 35
#define LL 200
#define GE3 105
#define LE 235

#define NTH 800    // 25 warps
#define BBLK 32
#define NCTA (NB / BBLK)   // 128

// fp16 m16n8k16, k16-PAIR packed B: ih0 stored 2 pairs; hh stored 7 pairs.
// REAL k16 counts: ih0 = 3 (pair0 + even half of pair1); hh = 13 (6 pairs + even half of pair6).
#define NP0 2
#define NPH 7
#define NTILES 75

// Output layout: concat(pred[B,T,K], mu[B,L], logvar[B,L], predY[B,1])
#define PRED_OFF ((size_t)0)
#define MU_OFF   ((size_t)NB * TT * KV)
#define LV_OFF   (MU_OFF + (size_t)NB * LL)
#define PY_OFF   (LV_OFF + (size_t)NB * LL)

__device__ uint4 g_b0ih[NTILES * NP0 * 32];
__device__ uint4 g_b0hh[NTILES * NPH * 32];
__device__ uint4 g_b1ih[NTILES * NPH * 32];
__device__ uint4 g_b1hh[NTILES * NPH * 32];

// SMEM layout (floats) — exact R12/R15 arrangement
#define HPAD 36
#define OFF_EMB 0        // 2240
#define OFF_CB  2240     // 1600
#define OFF_H1  3840     // 7200 (200 x 36 fp32)
#define OFF_H2  11040    // 7200
#define OFF_AXE 18240    // 1536 (4 k16 x 32 x 12)
#define OFF_AH1 19776    // 5376 (14 x 32 x 12)
#define OFF_AH2 25152    // 5376
#define OFF_TOK 30528    // 4096
#define SMEM_FLOATS 34624
// ---- post-encoder overlays (regions dead at time of use) ----
#define OFF_MUS 0        // 6400
#define OFF_W0  0        // 3675 dW_ih0[:,L:]
#define OFF_W1  3680     // 3675 dW_ih1
#define OFF_F2T 7360     // 2240 fc2^T [35][64]
#define OFF_T1  11040    // 6400 (over h2s)
#define OFF_ZS  18240    // 6400 (over axe+ah1)
#define OFF_GZ  25152    // 3360 (over ah2)
#define OFF_G1  28512    // 3360
#define OFF_HD  31872    // 1120
#define OFF_LW  32992    // 1120

// Fast transcendentals (MUFU-based)
__device__ __forceinline__ float sigm(float v) {
    return __fdividef(1.0f, 1.0f + __expf(-v));
}
__device__ __forceinline__ float tanh_fast(float x) {
    float e = __expf(2.0f * x);
    return fmaf(-2.0f, __fdividef(1.0f, e + 1.0f), 1.0f);
}

__device__ __forceinline__ void mma16(float (&c)[4], const uint32_t (&a)[4], uint2 b) {
    asm volatile(
        "mma.sync.aligned.m16n8k16.row.col.f32.f16.f16.f32 "
        "{%0,%1,%2,%3}, {%4,%5,%6,%7}, {%8,%9}, {%0,%1,%2,%3};"
        : "+f"(c[0]), "+f"(c[1]), "+f"(c[2]), "+f"(c[3])
        : "r"(a[0]), "r"(a[1]), "r"(a[2]), "r"(a[3]), "r"(b.x), "r"(b.y));
}

__device__ __forceinline__ uint32_t h2bits(float lo, float hi) {
    __half2 h = __floats2half2_rn(lo, hi);
    return *(uint32_t*)&h;
}

// ---- prep: pack weights into paired-k16 fp16 B-fragment layout ----
__global__ void pack_b16(const float* __restrict__ s0, const float* __restrict__ s1,
                         const float* __restrict__ s2, const float* __restrict__ s3) {
    int m = blockIdx.y;
    const float* src = (m == 0) ? s0 : (m == 1) ? s1 : (m == 2) ? s2 : s3;
    uint4* dst = (m == 0) ? g_b0ih : (m == 1) ? g_b0hh : (m == 2) ? g_b1ih : g_b1hh;
    int K  = (m == 0) ? EE : LL;
    int np = (m == 0) ? NP0 : NPH;
    int idx = blockIdx.x * blockDim.x + threadIdx.x;
    int total = NTILES * np * 32;
    if (idx >= total) return;
    int lane = idx & 31;
    int r = idx >> 5;
    int kp = r % np;  r /= np;
    int tile = r;
    int gid = lane >> 2, tig = lane & 3;
    int n = tile * 8 + gid;
    float w[8];
    #pragma unroll
    for (int half = 0; half < 2; half++) {
        int kA = (2 * kp + half) * 16 + 2 * tig;
        w[half * 4 + 0] = (kA     < K) ? src[n * K + kA]     : 0.0f;
        w[half * 4 + 1] = (kA + 1 < K) ? src[n * K + kA + 1] : 0.0f;
        w[half * 4 + 2] = (kA + 8 < K) ? src[n * K + kA + 8] : 0.0f;
        w[half * 4 + 3] = (kA + 9 < K) ? src[n * K + kA + 9] : 0.0f;
    }
    dst[idx] = make_uint4(h2bits(w[0], w[1]), h2bits(w[2], w[3]),
                          h2bits(w[4], w[5]), h2bits(w[6], w[7]));
}

// One full kp (2 k16) worth of MMAs, given loaded B and the A base ptr.
__device__ __forceinline__ void kp_mmas(const uint32_t* __restrict__ p0,
                                        uint4 br, uint4 bz, uint4 bn,
                                        float (&cr)[2][4], float (&cz)[2][4], float (&cn)[2][4])
{
    const uint32_t* p1 = p0 + 32 * 12;
    uint4 v00 = *(const uint4*)p0;
    uint4 v01 = *(const uint4*)(p0 + 4);
    uint4 v10 = *(const uint4*)p1;
    uint4 v11 = *(const uint4*)(p1 + 4);
    uint32_t ae0[4] = {v00.x, v00.y, v00.z, v00.w};
    uint32_t ae1[4] = {v01.x, v01.y, v01.z, v01.w};
    uint32_t ao0[4] = {v10.x, v10.y, v10.z, v10.w};
    uint32_t ao1[4] = {v11.x, v11.y, v11.z, v11.w};
    uint2 bre = make_uint2(br.x, br.y), bro = make_uint2(br.z, br.w);
    uint2 bze = make_uint2(bz.x, bz.y), bzo = make_uint2(bz.z, bz.w);
    uint2 bne = make_uint2(bn.x, bn.y), bno = make_uint2(bn.z, bn.w);
    mma16(cr[0], ae0, bre);  mma16(cr[1], ae1, bre);
    mma16(cz[0], ae0, bze);  mma16(cz[1], ae1, bze);
    mma16(cn[0], ae0, bne);  mma16(cn[1], ae1, bne);
    mma16(cr[0], ao0, bro);  mma16(cr[1], ao1, bro);
    mma16(cz[0], ao0, bzo);  mma16(cz[1], ao1, bzo);
    mma16(cn[0], ao0, bno);  mma16(cn[1], ao1, bno);
}

// MMA pass with HALF-PAIR TAIL: processes nFull full pairs then ONLY the even
// k16 of pair nFull (the odd k16 is all-zero padding -> skipping is bitwise
// identical). Saves 1 k16 of B loads + MMAs per pass (8.7% of encoder work).
__device__ __forceinline__ void enc_pass(const uint32_t* __restrict__ atfA,
                                         const uint4* __restrict__ B, int npStored, int nFull,
                                         float (&cr)[2][4], float (&cz)[2][4], float (&cn)[2][4],
                                         int wrp, int lane)
{
    const uint4* pr = B + (size_t)(wrp * npStored) * 32 + lane;
    const uint4* pz = pr + (size_t)25 * npStored * 32;
    const uint4* pn = pz + (size_t)25 * npStored * 32;
    int kp = 0;
    #pragma unroll 1
    for (; kp + 2 <= nFull; kp += 2) {
        uint4 br0 = pr[kp * 32];
        uint4 bz0 = pz[kp * 32];
        uint4 bn0 = pn[kp * 32];
        uint4 br1 = pr[kp * 32 + 32];
        uint4 bz1 = pz[kp * 32 + 32];
        uint4 bn1 = pn[kp * 32 + 32];
        kp_mmas(atfA + ((2 * kp) * 32 + lane) * 12,     br0, bz0, bn0, cr, cz, cn);
        kp_mmas(atfA + ((2 * kp + 2) * 32 + lane) * 12, br1, bz1, bn1, cr, cz, cn);
    }
    if (kp < nFull) {
        uint4 br = pr[kp * 32];
        uint4 bz = pz[kp * 32];
        uint4 bn = pn[kp * 32];
        kp_mmas(atfA + ((2 * kp) * 32 + lane) * 12, br, bz, bn, cr, cz, cn);
        kp++;
    }
    // half tail: even k16 of pair kp (uint2 = first 8B of the 16B slot)
    {
        uint2 br = *(const uint2*)(pr + kp * 32);
        uint2 bz = *(const uint2*)(pz + kp * 32);
        uint2 bn = *(const uint2*)(pn + kp * 32);
        const uint32_t* p0 = atfA + ((2 * kp) * 32 + lane) * 12;
        uint4 v00 = *(const uint4*)p0;
        uint4 v01 = *(const uint4*)(p0 + 4);
        uint32_t ae0[4] = {v00.x, v00.y, v00.z, v00.w};
        uint32_t ae1[4] = {v01.x, v01.y, v01.z, v01.w};
        mma16(cr[0], ae0, br);  mma16(cr[1], ae1, br);
        mma16(cz[0], ae0, bz);  mma16(cz[1], ae1, bz);
        mma16(cn[0], ae0, bn);  mma16(cn[1], ae1, bn);
    }
}

// Register GRU epilogue (R12-proven)
__device__ __forceinline__ void gru_epi(float* __restrict__ hb, uint32_t* __restrict__ atf_dst,
                                        const float* __restrict__ cb,
                                        float (&cr)[2][4], float (&cz)[2][4],
                                        float (&ci)[2][4], float (&ch)[2][4],
                                        int wrp, int lane)
{
    int gid = lane >> 2, tig = lane & 3;
    int j0 = 8 * wrp + 2 * tig;
    int k16d = wrp >> 1, khalf = wrp & 1;
    uint32_t* dst = atf_dst + (k16d * 32 + lane) * 12 + khalf * 2;
    float br0 = cb[j0], br1 = cb[j0 + 1];
    float bz0 = cb[200 + j0], bz1 = cb[200 + j0 + 1];
    float bi0 = cb[400 + j0], bi1 = cb[400 + j0 + 1];
    float bh0 = cb[600 + j0], bh1 = cb[600 + j0 + 1];
    #pragma unroll
    for (int m = 0; m < 2; m++) {
        uint32_t w[2];
        #pragma unroll
        for (int bh = 0; bh < 2; bh++) {
            int b = m * 16 + bh * 8 + gid;
            float hv[2];
            #pragma unroll
            for (int d = 0; d < 2; d++) {
                int i = bh * 2 + d;
                int j = j0 + d;
                float r = sigm(cr[m][i] + (d ? br1 : br0));
                float z = sigm(cz[m][i] + (d ? bz1 : bz0));
                float n = tanh_fast(ci[m][i] + (d ? bi1 : bi0) + r * (ch[m][i] + (d ? bh1 : bh0)));
                float ho = hb[j * HPAD + b];
                float hn = n + z * (ho - n);
                hb[j * HPAD + b] = hn;
                hv[d] = hn;
            }
            w[bh] = h2bits(hv[0], hv[1]);
        }
        *(uint2*)(dst + m * 4) = make_uint2(w[0], w[1]);
    }
}

extern "C" __global__ void __launch_bounds__(NTH, 1)
vae_all(const int* __restrict__ x, const float* __restrict__ emb,
        const float* __restrict__ eb_ih0, const float* __restrict__ eb_hh0,
        const float* __restrict__ eb_ih1, const float* __restrict__ eb_hh1,
        const float* __restrict__ dW_ih0, const float* __restrict__ db_ih0,
        const float* __restrict__ db_hh0,
        const float* __restrict__ dW_ih1, const float* __restrict__ db_ih1,
        const float* __restrict__ db_hh1,
        const float* __restrict__ fc11_w, const float* __restrict__ fc11_b,
        const float* __restrict__ fc12_w, const float* __restrict__ fc12_b,
        const float* __restrict__ p1_w,  const float* __restrict__ p1_b,
        const float* __restrict__ p2_w,  const float* __restrict__ p2_b,
        const float* __restrict__ fc2_w, const float* __restrict__ fc2_b,
        const float* __restrict__ eps,   float* __restrict__ out)
{
    extern __shared__ float sm[];
    float* emb_s = sm + OFF_EMB;
    float* cb_s  = sm + OFF_CB;
    float* h1s   = sm + OFF_H1;
    float* h2s   = sm + OFF_H2;
    uint32_t* axe = (uint32_t*)(sm + OFF_AXE);
    uint32_t* ah1 = (uint32_t*)(sm + OFF_AH1);
    uint32_t* ah2 = (uint32_t*)(sm + OFF_AH2);
    int* toks = (int*)(sm + OFF_TOK);

    const int tid = threadIdx.x;
    const int bg0 = blockIdx.x * BBLK;

    for (int i = tid; i < KV * EE; i += NTH) emb_s[i] = emb[i];
    for (int i = tid; i < 200 * HPAD; i += NTH) { h1s[i] = 0.0f; h2s[i] = 0.0f; }
    for (int i = tid; i < 4 * 32 * 12; i += NTH) axe[i] = 0u;
    for (int i = tid; i < 14 * 32 * 12; i += NTH) { ah1[i] = 0u; ah2[i] = 0u; }
    for (int i = tid; i < TT * 32; i += NTH) {
        int t = i >> 5, b = i & 31;
        toks[i] = x[(size_t)(bg0 + b) * TT + t];
    }
    for (int i = tid; i < 1600; i += NTH) {
        int l = i / 800, rem = i % 800, g = rem / 200, j = rem % 200;
        const float* bi = l ? eb_ih1 : eb_ih0;
        const float* bh = l ? eb_hh1 : eb_hh0;
        float v;
        if      (g == 0) v = bi[j] + bh[j];
        else if (g == 1) v = bi[200 + j] + bh[200 + j];
        else if (g == 2) v = bi[400 + j];
        else             v = bh[400 + j];
        cb_s[i] = v;
    }
    __syncthreads();

    const int lane = tid & 31;
    const int wrp  = tid >> 5;

    const int jt = tid >> 3;
    const int j0e = jt * 2;
    const int b0e = (tid & 7) * 4;

    // =====================  ENCODER (fp16 mma, half-pair tails)  =====================
    for (int t = 0; t < TT; t++) {
        if (tid < 576) {
            int kp = tid >> 5, b = tid & 31;
            int k = kp * 2;
            int tok = toks[t * 32 + b];
            float e0 = emb_s[tok * EE + k];
            float e1 = (k + 1 < EE) ? emb_s[tok * EE + k + 1] : 0.0f;
            int jj = k & 15, k16 = k >> 4;
            int tigp = (jj & 7) >> 1, khalf = jj >> 3;
            int mhalf = (b >> 3) & 1, mt = b >> 4, gidp = b & 7;
            axe[(k16 * 32 + gidp * 4 + tigp) * 12 + mt * 4 + khalf * 2 + mhalf] = h2bits(e0, e1);
        }
        __syncthreads();

        {   // ---- layer 0: ih = 1 full pair + half; hh = 6 full pairs + half ----
            float cr[2][4] = {}, cz[2][4] = {}, ci[2][4] = {}, ch[2][4] = {};
            enc_pass(axe, g_b0ih, NP0, 1, cr, cz, ci, wrp, lane);
            enc_pass(ah1, g_b0hh, NPH, 6, cr, cz, ch, wrp, lane);
            __syncthreads();
            gru_epi(h1s, ah1, cb_s, cr, cz, ci, ch, wrp, lane);
        }
        __syncthreads();
        {   // ---- layer 1 ----
            float cr[2][4] = {}, cz[2][4] = {}, ci[2][4] = {}, ch[2][4] = {};
            enc_pass(ah1, g_b1ih, NPH, 6, cr, cz, ci, wrp, lane);
            enc_pass(ah2, g_b1hh, NPH, 6, cr, cz, ch, wrp, lane);
            __syncthreads();
            gru_epi(h2s, ah2, cb_s + 800, cr, cz, ci, ch, wrp, lane);
        }
        __syncthreads();
    }

    float* mus   = sm + OFF_MUS;
    float* t1s   = sm + OFF_T1;
    float* zs    = sm + OFF_ZS;
    float* gzs   = sm + OFF_GZ;
    float* g1s   = sm + OFF_G1;
    float* hds   = sm + OFF_HD;
    float* lastw = sm + OFF_LW;
    float* w0s   = sm + OFF_W0;
    float* w1s   = sm + OFF_W1;
    float* f2t   = sm + OFF_F2T;

    // =====================  HEADS  =====================
    {
        float am[2][4], al[2][4];
        #pragma unroll
        for (int jj = 0; jj < 2; jj++) {
            float bm = fc11_b[j0e + jj], bl = fc12_b[j0e + jj];
            #pragma unroll
            for (int b = 0; b < 4; b++) { am[jj][b] = bm; al[jj][b] = bl; }
        }
        const float* w1 = fc11_w + j0e * LL;
        const float* w2 = fc12_w + j0e * LL;
        #pragma unroll 1
        for (int k = 0; k < LL; k += 2) {
            float4 u = *(const float4*)(h2s + k * HPAD + b0e);
            float4 w = *(const float4*)(h2s + (k + 1) * HPAD + b0e);
            float va[4] = {u.x, u.y, u.z, u.w};
            float vb[4] = {w.x, w.y, w.z, w.w};
            #pragma unroll
            for (int jj = 0; jj < 2; jj++) {
                float2 a = *(const float2*)(w1 + jj * LL + k);
                float2 c = *(const float2*)(w2 + jj * LL + k);
                #pragma unroll
                for (int b = 0; b < 4; b++) {
                    am[jj][b] = fmaf(a.x, va[b], am[jj][b]);
                    am[jj][b] = fmaf(a.y, vb[b], am[jj][b]);
                    al[jj][b] = fmaf(c.x, va[b], al[jj][b]);
                    al[jj][b] = fmaf(c.y, vb[b], al[jj][b]);
                }
            }
        }
        __syncthreads();   // h2s reads done before overlays
        #pragma unroll
        for (int jj = 0; jj < 2; jj++)
            #pragma unroll
            for (int b = 0; b < 4; b++) {
                int j = j0e + jj, bb = b0e + b, bg = bg0 + bb;
                float m = am[jj][b], lv = al[jj][b];
                out[MU_OFF + (size_t)bg * LL + j] = m;
                out[LV_OFF + (size_t)bg * LL + j] = lv;
                mus[j * 32 + bb] = m;
                zs[j * 32 + bb] = fmaf(eps[(size_t)bg * LL + j], expf(0.5f * lv), m);
            }
        __syncthreads();
    }
    {   // t1 = relu(mu @ p1^T + b)
        float aa[2][4];
        #pragma unroll
        for (int jj = 0; jj < 2; jj++) {
            float bv = p1_b[j0e + jj];
            #pragma unroll
            for (int b = 0; b < 4; b++) aa[jj][b] = bv;
        }
        const float* w1 = p1_w + j0e * LL;
        #pragma unroll 1
        for (int k = 0; k < LL; k += 2) {
            float4 u = *(const float4*)(mus + k * 32 + b0e);
            float4 w = *(const float4*)(mus + (k + 1) * 32 + b0e);
            float va[4] = {u.x, u.y, u.z, u.w};
            float vb[4] = {w.x, w.y, w.z, w.w};
            #pragma unroll
            for (int jj = 0; jj < 2; jj++) {
                float2 a = *(const float2*)(w1 + jj * LL + k);
                #pragma unroll
                for (int b = 0; b < 4; b++) {
                    aa[jj][b] = fmaf(a.x, va[b], aa[jj][b]);
                    aa[jj][b] = fmaf(a.y, vb[b], aa[jj][b]);
                }
            }
        }
        #pragma unroll
        for (int jj = 0; jj < 2; jj++)
            #pragma unroll
            for (int b = 0; b < 4; b++)
                t1s[(j0e + jj) * 32 + b0e + b] = fmaxf(aa[jj][b], 0.0f);
        __syncthreads();   // mus reads done; t1s visible
    }
    if (tid < 32) {
        float a = p2_b[0];
        for (int j = 0; j < LL; j++) a = fmaf(p2_w[j], t1s[j * 32 + tid], a);
        out[PY_OFF + bg0 + tid] = a;
    }
    for (int idx = tid; idx < GE3 * 32; idx += NTH) {
        int g = idx >> 5, b = idx & 31;
        float a = db_ih0[g];
        const float* w = dW_ih0 + g * LE;
        #pragma unroll 4
        for (int k = 0; k < LL; k++) a = fmaf(zs[k * 32 + b], w[k], a);
        gzs[idx] = a;
    }
    for (int i = tid; i < GE3 * EE; i += NTH) {
        w0s[i] = dW_ih0[(i / EE) * LE + LL + (i % EE)];
        w1s[i] = dW_ih1[i];
    }
    for (int i = tid; i < EE * KV; i += NTH)
        f2t[i] = fc2_w[(i & 63) * EE + (i >> 6)];
    for (int i = tid; i < EE * 32; i += NTH) lastw[i] = 0.0f;
    __syncthreads();

    // =====================  DECODER (fp32 SIMT, vectorized x4)  =====================
    for (int t = 0; t < TT; t++) {
        for (int idx = tid; idx < GE3 * 8; idx += NTH) {
            int g = idx >> 3, b0 = (idx & 7) * 4;
            float4 acc = *(const float4*)(gzs + g * 32 + b0);
            const float* w = w0s + g * EE;
            #pragma unroll 5
            for (int k = 0; k < EE; k++) {
                float4 a = *(const float4*)(lastw + k * 32 + b0);
                float wv = w[k];
                acc.x = fmaf(wv, a.x, acc.x);
                acc.y = fmaf(wv, a.y, acc.y);
                acc.z = fmaf(wv, a.z, acc.z);
                acc.w = fmaf(wv, a.w, acc.w);
            }
            *(float4*)(g1s + g * 32 + b0) = acc;
        }
        __syncthreads();
        for (int idx = tid; idx < EE * 32; idx += NTH) {
            int e = idx >> 5, b = idx & 31;
            float r  = sigm(g1s[e * 32 + b] + db_hh0[e]);
            float zg = sigm(g1s[(EE + e) * 32 + b] + db_hh0[EE + e]);
            float n  = tanh_fast(fmaf(r, db_hh0[2 * EE + e], g1s[(2 * EE + e) * 32 + b]));
            hds[idx] = (1.0f - zg) * n;
        }
        __syncthreads();
        for (int idx = tid; idx < GE3 * 8; idx += NTH) {
            int g = idx >> 3, b0 = (idx & 7) * 4;
            float bv = db_ih1[g];
            float4 acc = make_float4(bv, bv, bv, bv);
            const float* w = w1s + g * EE;
            #pragma unroll 5
            for (int k = 0; k < EE; k++) {
                float4 a = *(const float4*)(hds + k * 32 + b0);
                float wv = w[k];
                acc.x = fmaf(wv, a.x, acc.x);
                acc.y = fmaf(wv, a.y, acc.y);
                acc.z = fmaf(wv, a.z, acc.z);
                acc.w = fmaf(wv, a.w, acc.w);
            }
            *(float4*)(g1s + g * 32 + b0) = acc;
        }
        __syncthreads();
        for (int idx = tid; idx < EE * 32; idx += NTH) {
            int e = idx >> 5, b = idx & 31;
            float r  = sigm(g1s[e * 32 + b] + db_hh1[e]);
            float zg = sigm(g1s[(EE + e) * 32 + b] + db_hh1[EE + e]);
            float n  = tanh_fast(fmaf(r, db_hh1[2 * EE + e], g1s[(2 * EE + e) * 32 + b]));
            lastw[idx] = (1.0f - zg) * n;
        }
        __syncthreads();
        // fc2 reads lastw/f2t only; next gi1 writes g1s whose prior readers were
        // ordered by the sync above -> no trailing barrier (R8-proven safe).
        if (tid < 512) {
            int b = tid >> 4, kk0 = (tid & 15) * 4;
            float4 acc = *(const float4*)(fc2_b + kk0);
            #pragma unroll 5
            for (int e = 0; e < EE; e++) {
                float a = lastw[e * 32 + b];
                float4 wv = *(const float4*)(f2t + e * KV + kk0);
                acc.x = fmaf(wv.x, a, acc.x);
                acc.y = fmaf(wv.y, a, acc.y);
                acc.z = fmaf(wv.z, a, acc.z);
                acc.w = fmaf(wv.w, a, acc.w);
            }
            *(float4*)(out + PRED_OFF + ((size_t)(bg0 + b) * TT + t) * KV + kk0) = acc;
        }
    }
}

extern "C" void kernel_launch(void* const* d_in, const int* in_sizes, int n_in,
                              void* d_out, int out_size) {
    (void)in_sizes; (void)n_in; (void)out_size;
    const int*   x       = (const int*)  d_in[0];
    const float* emb     = (const float*)d_in[1];
    const float* eW_ih0  = (const float*)d_in[2];
    const float* eW_hh0  = (const float*)d_in[3];
    const float* eb_ih0  = (const float*)d_in[4];
    const float* eb_hh0  = (const float*)d_in[5];
    const float* eW_ih1  = (const float*)d_in[6];
    const float* eW_hh1  = (const float*)d_in[7];
    const float* eb_ih1  = (const float*)d_in[8];
    const float* eb_hh1  = (const float*)d_in[9];
    const float* dW_ih0  = (const float*)d_in[10];
    const float* db_ih0  = (const float*)d_in[12];
    const float* db_hh0  = (const float*)d_in[13];
    const float* dW_ih1  = (const float*)d_in[14];
    const float* db_ih1  = (const float*)d_in[16];
    const float* db_hh1  = (const float*)d_in[17];
    const float* fc11_w  = (const float*)d_in[18];
    const float* fc11_b  = (const float*)d_in[19];
    const float* fc12_w  = (const float*)d_in[20];
    const float* fc12_b  = (const float*)d_in[21];
    const float* p1_w    = (const float*)d_in[22];
    const float* p1_b    = (const float*)d_in[23];
    const float* p2_w    = (const float*)d_in[24];
    const float* p2_b    = (const float*)d_in[25];
    const float* fc2_w   = (const float*)d_in[26];
    const float* fc2_b   = (const float*)d_in[27];
    const float* eps     = (const float*)d_in[28];

    {
        int maxtot = NTILES * NPH * 32;  // 16800
        dim3 grid((maxtot + 255) / 256, 4);
        pack_b16<<<grid, 256>>>(eW_ih0, eW_hh0, eW_ih1, eW_hh1);
    }

    cudaFuncSetAttribute((const void*)vae_all,
                         cudaFuncAttributeMaxDynamicSharedMemorySize,
                         SMEM_FLOATS * (int)sizeof(float));

    vae_all<<<NCTA, NTH, SMEM_FLOATS * sizeof(float)>>>(
        x, emb, eb_ih0, eb_hh0, eb_ih1, eb_hh1,
        dW_ih0, db_ih0, db_hh0, dW_ih1, db_ih1, db_hh1,
        fc11_w, fc11_b, fc12_w, fc12_b, p1_w, p1_b, p2_w, p2_b,
        fc2_w, fc2_b, eps, (float*)d_out);
}

// round 17
// speedup vs baseline: 3.6555x; 1.1135x over previous
#include <cuda_runtime.h>
#include <cuda_fp16.h>
#include <math.h>
#include <stdint.h>

// Problem dims
#define NB 4096
#define TT 128
#define KV 64
#define EE 35
#define LL 200
#define GE3 105
#define LE 235

#define NTH 800    // 25 warps
#define BBLK 32
#define NCTA (NB / BBLK)   // 128

// fp16 m16n8k16, k16-PAIR packed B: ih0 stored 2 pairs; hh stored 7 pairs.
// REAL k16 counts: ih0 = 3 (1 full pair + even half); hh = 13 (6 pairs + even half).
#define NP0 2
#define NPH 7
#define NTILES 75

// Output layout: concat(pred[B,T,K], mu[B,L], logvar[B,L], predY[B,1])
#define PRED_OFF ((size_t)0)
#define MU_OFF   ((size_t)NB * TT * KV)
#define LV_OFF   (MU_OFF + (size_t)NB * LL)
#define PY_OFF   (LV_OFF + (size_t)NB * LL)

__device__ uint4 g_b0ih[NTILES * NP0 * 32];
__device__ uint4 g_b0hh[NTILES * NPH * 32];
__device__ uint4 g_b1ih[NTILES * NPH * 32];
__device__ uint4 g_b1hh[NTILES * NPH * 32];

// SMEM layout (floats) — R12/R16 arrangement
#define HPAD 36
#define OFF_EMB 0        // 2240
#define OFF_CB  2240     // 1600
#define OFF_H1  3840     // 7200 (200 x 36 fp32)
#define OFF_H2  11040    // 7200
#define OFF_AXE 18240    // 1536 (4 k16 x 32 x 12)
#define OFF_AH1 19776    // 5376 (14 x 32 x 12)
#define OFF_AH2 25152    // 5376
#define OFF_TOK 30528    // 4096
#define SMEM_FLOATS 34624
// ---- post-encoder overlays (regions dead at time of use) ----
#define OFF_MUS 0        // 6400
#define OFF_W0  0        // 3675 dW_ih0[:,L:]
#define OFF_W1  3680     // 3675 dW_ih1
#define OFF_F2T 7360     // 2240 fc2^T [35][64]
#define OFF_T1  11040    // 6400 (over h2s)
#define OFF_ZS  18240    // 6400 (over axe+ah1)
#define OFF_GZ  25152    // 3360 (over ah2)
#define OFF_HD  28512    // 1120
#define OFF_LW  29632    // 1120

// Fast transcendentals (MUFU-based)
__device__ __forceinline__ float sigm(float v) {
    return __fdividef(1.0f, 1.0f + __expf(-v));
}
__device__ __forceinline__ float tanh_fast(float x) {
    float e = __expf(2.0f * x);
    return fmaf(-2.0f, __fdividef(1.0f, e + 1.0f), 1.0f);
}

__device__ __forceinline__ void mma16(float (&c)[4], const uint32_t (&a)[4], uint2 b) {
    asm volatile(
        "mma.sync.aligned.m16n8k16.row.col.f32.f16.f16.f32 "
        "{%0,%1,%2,%3}, {%4,%5,%6,%7}, {%8,%9}, {%0,%1,%2,%3};"
        : "+f"(c[0]), "+f"(c[1]), "+f"(c[2]), "+f"(c[3])
        : "r"(a[0]), "r"(a[1]), "r"(a[2]), "r"(a[3]), "r"(b.x), "r"(b.y));
}

__device__ __forceinline__ uint32_t h2bits(float lo, float hi) {
    __half2 h = __floats2half2_rn(lo, hi);
    return *(uint32_t*)&h;
}

// ---- prep: pack weights into paired-k16 fp16 B-fragment layout ----
__global__ void pack_b16(const float* __restrict__ s0, const float* __restrict__ s1,
                         const float* __restrict__ s2, const float* __restrict__ s3) {
    int m = blockIdx.y;
    const float* src = (m == 0) ? s0 : (m == 1) ? s1 : (m == 2) ? s2 : s3;
    uint4* dst = (m == 0) ? g_b0ih : (m == 1) ? g_b0hh : (m == 2) ? g_b1ih : g_b1hh;
    int K  = (m == 0) ? EE : LL;
    int np = (m == 0) ? NP0 : NPH;
    int idx = blockIdx.x * blockDim.x + threadIdx.x;
    int total = NTILES * np * 32;
    if (idx >= total) return;
    int lane = idx & 31;
    int r = idx >> 5;
    int kp = r % np;  r /= np;
    int tile = r;
    int gid = lane >> 2, tig = lane & 3;
    int n = tile * 8 + gid;
    float w[8];
    #pragma unroll
    for (int half = 0; half < 2; half++) {
        int kA = (2 * kp + half) * 16 + 2 * tig;
        w[half * 4 + 0] = (kA     < K) ? src[n * K + kA]     : 0.0f;
        w[half * 4 + 1] = (kA + 1 < K) ? src[n * K + kA + 1] : 0.0f;
        w[half * 4 + 2] = (kA + 8 < K) ? src[n * K + kA + 8] : 0.0f;
        w[half * 4 + 3] = (kA + 9 < K) ? src[n * K + kA + 9] : 0.0f;
    }
    dst[idx] = make_uint4(h2bits(w[0], w[1]), h2bits(w[2], w[3]),
                          h2bits(w[4], w[5]), h2bits(w[6], w[7]));
}

// One full kp (2 k16) of MMAs, given loaded B and the A base ptr.
__device__ __forceinline__ void kp_mmas(const uint32_t* __restrict__ p0,
                                        uint4 br, uint4 bz, uint4 bn,
                                        float (&cr)[2][4], float (&cz)[2][4], float (&cn)[2][4])
{
    const uint32_t* p1 = p0 + 32 * 12;
    uint4 v00 = *(const uint4*)p0;
    uint4 v01 = *(const uint4*)(p0 + 4);
    uint4 v10 = *(const uint4*)p1;
    uint4 v11 = *(const uint4*)(p1 + 4);
    uint32_t ae0[4] = {v00.x, v00.y, v00.z, v00.w};
    uint32_t ae1[4] = {v01.x, v01.y, v01.z, v01.w};
    uint32_t ao0[4] = {v10.x, v10.y, v10.z, v10.w};
    uint32_t ao1[4] = {v11.x, v11.y, v11.z, v11.w};
    uint2 bre = make_uint2(br.x, br.y), bro = make_uint2(br.z, br.w);
    uint2 bze = make_uint2(bz.x, bz.y), bzo = make_uint2(bz.z, bz.w);
    uint2 bne = make_uint2(bn.x, bn.y), bno = make_uint2(bn.z, bn.w);
    mma16(cr[0], ae0, bre);  mma16(cr[1], ae1, bre);
    mma16(cz[0], ae0, bze);  mma16(cz[1], ae1, bze);
    mma16(cn[0], ae0, bne);  mma16(cn[1], ae1, bne);
    mma16(cr[0], ao0, bro);  mma16(cr[1], ao1, bro);
    mma16(cz[0], ao0, bzo);  mma16(cz[1], ao1, bzo);
    mma16(cn[0], ao0, bno);  mma16(cn[1], ao1, bno);
}

// MMA pass with HALF-PAIR TAIL (R16-proven): skips the all-zero odd k16 of the
// last pair -> bitwise identical with 1 k16 less work per pass.
__device__ __forceinline__ void enc_pass(const uint32_t* __restrict__ atfA,
                                         const uint4* __restrict__ B, int npStored, int nFull,
                                         float (&cr)[2][4], float (&cz)[2][4], float (&cn)[2][4],
                                         int wrp, int lane)
{
    const uint4* pr = B + (size_t)(wrp * npStored) * 32 + lane;
    const uint4* pz = pr + (size_t)25 * npStored * 32;
    const uint4* pn = pz + (size_t)25 * npStored * 32;
    int kp = 0;
    #pragma unroll 1
    for (; kp + 2 <= nFull; kp += 2) {
        uint4 br0 = pr[kp * 32];
        uint4 bz0 = pz[kp * 32];
        uint4 bn0 = pn[kp * 32];
        uint4 br1 = pr[kp * 32 + 32];
        uint4 bz1 = pz[kp * 32 + 32];
        uint4 bn1 = pn[kp * 32 + 32];
        kp_mmas(atfA + ((2 * kp) * 32 + lane) * 12,     br0, bz0, bn0, cr, cz, cn);
        kp_mmas(atfA + ((2 * kp + 2) * 32 + lane) * 12, br1, bz1, bn1, cr, cz, cn);
    }
    if (kp < nFull) {
        uint4 br = pr[kp * 32];
        uint4 bz = pz[kp * 32];
        uint4 bn = pn[kp * 32];
        kp_mmas(atfA + ((2 * kp) * 32 + lane) * 12, br, bz, bn, cr, cz, cn);
        kp++;
    }
    {   // half tail: even k16 of pair kp
        uint2 br = *(const uint2*)(pr + kp * 32);
        uint2 bz = *(const uint2*)(pz + kp * 32);
        uint2 bn = *(const uint2*)(pn + kp * 32);
        const uint32_t* p0 = atfA + ((2 * kp) * 32 + lane) * 12;
        uint4 v00 = *(const uint4*)p0;
        uint4 v01 = *(const uint4*)(p0 + 4);
        uint32_t ae0[4] = {v00.x, v00.y, v00.z, v00.w};
        uint32_t ae1[4] = {v01.x, v01.y, v01.z, v01.w};
        mma16(cr[0], ae0, br);  mma16(cr[1], ae1, br);
        mma16(cz[0], ae0, bz);  mma16(cz[1], ae1, bz);
        mma16(cn[0], ae0, bn);  mma16(cn[1], ae1, bn);
    }
}

// Register GRU epilogue (R12-proven)
__device__ __forceinline__ void gru_epi(float* __restrict__ hb, uint32_t* __restrict__ atf_dst,
                                        const float* __restrict__ cb,
                                        float (&cr)[2][4], float (&cz)[2][4],
                                        float (&ci)[2][4], float (&ch)[2][4],
                                        int wrp, int lane)
{
    int gid = lane >> 2, tig = lane & 3;
    int j0 = 8 * wrp + 2 * tig;
    int k16d = wrp >> 1, khalf = wrp & 1;
    uint32_t* dst = atf_dst + (k16d * 32 + lane) * 12 + khalf * 2;
    float br0 = cb[j0], br1 = cb[j0 + 1];
    float bz0 = cb[200 + j0], bz1 = cb[200 + j0 + 1];
    float bi0 = cb[400 + j0], bi1 = cb[400 + j0 + 1];
    float bh0 = cb[600 + j0], bh1 = cb[600 + j0 + 1];
    #pragma unroll
    for (int m = 0; m < 2; m++) {
        uint32_t w[2];
        #pragma unroll
        for (int bh = 0; bh < 2; bh++) {
            int b = m * 16 + bh * 8 + gid;
            float hv[2];
            #pragma unroll
            for (int d = 0; d < 2; d++) {
                int i = bh * 2 + d;
                int j = j0 + d;
                float r = sigm(cr[m][i] + (d ? br1 : br0));
                float z = sigm(cz[m][i] + (d ? bz1 : bz0));
                float n = tanh_fast(ci[m][i] + (d ? bi1 : bi0) + r * (ch[m][i] + (d ? bh1 : bh0)));
                float ho = hb[j * HPAD + b];
                float hn = n + z * (ho - n);
                hb[j * HPAD + b] = hn;
                hv[d] = hn;
            }
            w[bh] = h2bits(hv[0], hv[1]);
        }
        *(uint2*)(dst + m * 4) = make_uint2(w[0], w[1]);
    }
}

// Gather step-t embeddings into fragment layout.
__device__ __forceinline__ void gather_axe(uint32_t* __restrict__ axe,
                                           const float* __restrict__ emb_s,
                                           const int* __restrict__ toks,
                                           int t, int tid)
{
    if (tid < 576) {
        int kp = tid >> 5, b = tid & 31;
        int k = kp * 2;
        int tok = toks[t * 32 + b];
        float e0 = emb_s[tok * EE + k];
        float e1 = (k + 1 < EE) ? emb_s[tok * EE + k + 1] : 0.0f;
        int jj = k & 15, k16 = k >> 4;
        int tigp = (jj & 7) >> 1, khalf = jj >> 3;
        int mhalf = (b >> 3) & 1, mt = b >> 4, gidp = b & 7;
        axe[(k16 * 32 + gidp * 4 + tigp) * 12 + mt * 4 + khalf * 2 + mhalf] = h2bits(e0, e1);
    }
}

extern "C" __global__ void __launch_bounds__(NTH, 1)
vae_all(const int* __restrict__ x, const float* __restrict__ emb,
        const float* __restrict__ eb_ih0, const float* __restrict__ eb_hh0,
        const float* __restrict__ eb_ih1, const float* __restrict__ eb_hh1,
        const float* __restrict__ dW_ih0, const float* __restrict__ db_ih0,
        const float* __restrict__ db_hh0,
        const float* __restrict__ dW_ih1, const float* __restrict__ db_ih1,
        const float* __restrict__ db_hh1,
        const float* __restrict__ fc11_w, const float* __restrict__ fc11_b,
        const float* __restrict__ fc12_w, const float* __restrict__ fc12_b,
        const float* __restrict__ p1_w,  const float* __restrict__ p1_b,
        const float* __restrict__ p2_w,  const float* __restrict__ p2_b,
        const float* __restrict__ fc2_w, const float* __restrict__ fc2_b,
        const float* __restrict__ eps,   float* __restrict__ out)
{
    extern __shared__ float sm[];
    float* emb_s = sm + OFF_EMB;
    float* cb_s  = sm + OFF_CB;
    float* h1s   = sm + OFF_H1;
    float* h2s   = sm + OFF_H2;
    uint32_t* axe = (uint32_t*)(sm + OFF_AXE);
    uint32_t* ah1 = (uint32_t*)(sm + OFF_AH1);
    uint32_t* ah2 = (uint32_t*)(sm + OFF_AH2);
    int* toks = (int*)(sm + OFF_TOK);

    const int tid = threadIdx.x;
    const int bg0 = blockIdx.x * BBLK;

    for (int i = tid; i < KV * EE; i += NTH) emb_s[i] = emb[i];
    for (int i = tid; i < 200 * HPAD; i += NTH) { h1s[i] = 0.0f; h2s[i] = 0.0f; }
    for (int i = tid; i < 4 * 32 * 12; i += NTH) axe[i] = 0u;
    for (int i = tid; i < 14 * 32 * 12; i += NTH) { ah1[i] = 0u; ah2[i] = 0u; }
    for (int i = tid; i < TT * 32; i += NTH) {
        int t = i >> 5, b = i & 31;
        toks[i] = x[(size_t)(bg0 + b) * TT + t];
    }
    for (int i = tid; i < 1600; i += NTH) {
        int l = i / 800, rem = i % 800, g = rem / 200, j = rem % 200;
        const float* bi = l ? eb_ih1 : eb_ih0;
        const float* bh = l ? eb_hh1 : eb_hh0;
        float v;
        if      (g == 0) v = bi[j] + bh[j];
        else if (g == 1) v = bi[200 + j] + bh[200 + j];
        else if (g == 2) v = bi[400 + j];
        else             v = bh[400 + j];
        cb_s[i] = v;
    }
    __syncthreads();

    const int lane = tid & 31;
    const int wrp  = tid >> 5;

    const int jt = tid >> 3;
    const int j0e = jt * 2;
    const int b0e = (tid & 7) * 4;

    // =====================  ENCODER (4 syncs/step, gather folded)  =====================
    gather_axe(axe, emb_s, toks, 0, tid);
    __syncthreads();
    for (int t = 0; t < TT; t++) {
        {   // ---- layer 0: ih = 1 full pair + half; hh = 6 full pairs + half ----
            float cr[2][4] = {}, cz[2][4] = {}, ci[2][4] = {}, ch[2][4] = {};
            enc_pass(axe, g_b0ih, NP0, 1, cr, cz, ci, wrp, lane);
            enc_pass(ah1, g_b0hh, NPH, 6, cr, cz, ch, wrp, lane);
            __syncthreads();
            gru_epi(h1s, ah1, cb_s, cr, cz, ci, ch, wrp, lane);
        }
        __syncthreads();
        {   // ---- layer 1 (+ gather t+1 overlapped with epilogue) ----
            float cr[2][4] = {}, cz[2][4] = {}, ci[2][4] = {}, ch[2][4] = {};
            enc_pass(ah1, g_b1ih, NPH, 6, cr, cz, ci, wrp, lane);
            enc_pass(ah2, g_b1hh, NPH, 6, cr, cz, ch, wrp, lane);
            __syncthreads();
            gru_epi(h2s, ah2, cb_s + 800, cr, cz, ci, ch, wrp, lane);
            if (t + 1 < TT) gather_axe(axe, emb_s, toks, t + 1, tid);
        }
        __syncthreads();
    }

    float* mus   = sm + OFF_MUS;
    float* t1s   = sm + OFF_T1;
    float* zs    = sm + OFF_ZS;
    float* gzs   = sm + OFF_GZ;
    float* hds   = sm + OFF_HD;
    float* lastw = sm + OFF_LW;
    float* w0s   = sm + OFF_W0;
    float* w1s   = sm + OFF_W1;
    float* f2t   = sm + OFF_F2T;

    // =====================  HEADS  =====================
    {
        float am[2][4], al[2][4];
        #pragma unroll
        for (int jj = 0; jj < 2; jj++) {
            float bm = fc11_b[j0e + jj], bl = fc12_b[j0e + jj];
            #pragma unroll
            for (int b = 0; b < 4; b++) { am[jj][b] = bm; al[jj][b] = bl; }
        }
        const float* w1 = fc11_w + j0e * LL;
        const float* w2 = fc12_w + j0e * LL;
        #pragma unroll 1
        for (int k = 0; k < LL; k += 2) {
            float4 u = *(const float4*)(h2s + k * HPAD + b0e);
            float4 w = *(const float4*)(h2s + (k + 1) * HPAD + b0e);
            float va[4] = {u.x, u.y, u.z, u.w};
            float vb[4] = {w.x, w.y, w.z, w.w};
            #pragma unroll
            for (int jj = 0; jj < 2; jj++) {
                float2 a = *(const float2*)(w1 + jj * LL + k);
                float2 c = *(const float2*)(w2 + jj * LL + k);
                #pragma unroll
                for (int b = 0; b < 4; b++) {
                    am[jj][b] = fmaf(a.x, va[b], am[jj][b]);
                    am[jj][b] = fmaf(a.y, vb[b], am[jj][b]);
                    al[jj][b] = fmaf(c.x, va[b], al[jj][b]);
                    al[jj][b] = fmaf(c.y, vb[b], al[jj][b]);
                }
            }
        }
        __syncthreads();   // h2s reads done before overlays
        #pragma unroll
        for (int jj = 0; jj < 2; jj++)
            #pragma unroll
            for (int b = 0; b < 4; b++) {
                int j = j0e + jj, bb = b0e + b, bg = bg0 + bb;
                float m = am[jj][b], lv = al[jj][b];
                out[MU_OFF + (size_t)bg * LL + j] = m;
                out[LV_OFF + (size_t)bg * LL + j] = lv;
                mus[j * 32 + bb] = m;
                zs[j * 32 + bb] = fmaf(eps[(size_t)bg * LL + j], expf(0.5f * lv), m);
            }
        __syncthreads();
    }
    {   // t1 = relu(mu @ p1^T + b)
        float aa[2][4];
        #pragma unroll
        for (int jj = 0; jj < 2; jj++) {
            float bv = p1_b[j0e + jj];
            #pragma unroll
            for (int b = 0; b < 4; b++) aa[jj][b] = bv;
        }
        const float* w1 = p1_w + j0e * LL;
        #pragma unroll 1
        for (int k = 0; k < LL; k += 2) {
            float4 u = *(const float4*)(mus + k * 32 + b0e);
            float4 w = *(const float4*)(mus + (k + 1) * 32 + b0e);
            float va[4] = {u.x, u.y, u.z, u.w};
            float vb[4] = {w.x, w.y, w.z, w.w};
            #pragma unroll
            for (int jj = 0; jj < 2; jj++) {
                float2 a = *(const float2*)(w1 + jj * LL + k);
                #pragma unroll
                for (int b = 0; b < 4; b++) {
                    aa[jj][b] = fmaf(a.x, va[b], aa[jj][b]);
                    aa[jj][b] = fmaf(a.y, vb[b], aa[jj][b]);
                }
            }
        }
        #pragma unroll
        for (int jj = 0; jj < 2; jj++)
            #pragma unroll
            for (int b = 0; b < 4; b++)
                t1s[(j0e + jj) * 32 + b0e + b] = fmaxf(aa[jj][b], 0.0f);
        __syncthreads();   // mus reads done -> weight staging may overwrite
    }
    if (tid < 32) {
        float a = p2_b[0];
        for (int j = 0; j < LL; j++) a = fmaf(p2_w[j], t1s[j * 32 + tid], a);
        out[PY_OFF + bg0 + tid] = a;
    }
    for (int idx = tid; idx < GE3 * 32; idx += NTH) {
        int g = idx >> 5, b = idx & 31;
        float a = db_ih0[g];
        const float* w = dW_ih0 + g * LE;
        #pragma unroll 4
        for (int k = 0; k < LL; k++) a = fmaf(zs[k * 32 + b], w[k], a);
        gzs[idx] = a;
    }
    for (int i = tid; i < GE3 * EE; i += NTH) {
        w0s[i] = dW_ih0[(i / EE) * LE + LL + (i % EE)];
        w1s[i] = dW_ih1[i];
    }
    for (int i = tid; i < EE * KV; i += NTH)
        f2t[i] = fc2_w[(i & 63) * EE + (i >> 6)];
    for (int i = tid; i < EE * 32; i += NTH) lastw[i] = 0.0f;
    __syncthreads();

    // ==========  DECODER (fused GRU phases: 2 syncs/step, no g1s round-trip)  ==========
    for (int t = 0; t < TT; t++) {
        // GRU1 fused: unit = (e, 2-batch). gi = gzs + lastw @ w0s, act in-register.
        if (tid < EE * 16) {
            int e = tid >> 4, bp = (tid & 15) * 2;
            float2 ar = *(const float2*)(gzs + e * 32 + bp);
            float2 az = *(const float2*)(gzs + (EE + e) * 32 + bp);
            float2 an = *(const float2*)(gzs + (2 * EE + e) * 32 + bp);
            const float* wr = w0s + e * EE;
            const float* wz = w0s + (EE + e) * EE;
            const float* wn = w0s + (2 * EE + e) * EE;
            #pragma unroll 5
            for (int k = 0; k < EE; k++) {
                float2 a = *(const float2*)(lastw + k * 32 + bp);
                float r = wr[k], z = wz[k], n = wn[k];
                ar.x = fmaf(r, a.x, ar.x);  ar.y = fmaf(r, a.y, ar.y);
                az.x = fmaf(z, a.x, az.x);  az.y = fmaf(z, a.y, az.y);
                an.x = fmaf(n, a.x, an.x);  an.y = fmaf(n, a.y, an.y);
            }
            float br = db_hh0[e], bz = db_hh0[EE + e], bn = db_hh0[2 * EE + e];
            float r0 = sigm(ar.x + br), r1 = sigm(ar.y + br);
            float z0 = sigm(az.x + bz), z1 = sigm(az.y + bz);
            float n0 = tanh_fast(fmaf(r0, bn, an.x));
            float n1 = tanh_fast(fmaf(r1, bn, an.y));
            hds[e * 32 + bp]     = (1.0f - z0) * n0;
            hds[e * 32 + bp + 1] = (1.0f - z1) * n1;
        }
        __syncthreads();
        // GRU2 fused: gi = db_ih1 + hds @ w1s, act in-register -> lastw
        if (tid < EE * 16) {
            int e = tid >> 4, bp = (tid & 15) * 2;
            float bir = db_ih1[e], biz = db_ih1[EE + e], bin = db_ih1[2 * EE + e];
            float2 ar = make_float2(bir, bir);
            float2 az = make_float2(biz, biz);
            float2 an = make_float2(bin, bin);
            const float* wr = w1s + e * EE;
            const float* wz = w1s + (EE + e) * EE;
            const float* wn = w1s + (2 * EE + e) * EE;
            #pragma unroll 5
            for (int k = 0; k < EE; k++) {
                float2 a = *(const float2*)(hds + k * 32 + bp);
                float r = wr[k], z = wz[k], n = wn[k];
                ar.x = fmaf(r, a.x, ar.x);  ar.y = fmaf(r, a.y, ar.y);
                az.x = fmaf(z, a.x, az.x);  az.y = fmaf(z, a.y, az.y);
                an.x = fmaf(n, a.x, an.x);  an.y = fmaf(n, a.y, an.y);
            }
            float br = db_hh1[e], bz = db_hh1[EE + e], bn = db_hh1[2 * EE + e];
            float r0 = sigm(ar.x + br), r1 = sigm(ar.y + br);
            float z0 = sigm(az.x + bz), z1 = sigm(az.y + bz);
            float n0 = tanh_fast(fmaf(r0, bn, an.x));
            float n1 = tanh_fast(fmaf(r1, bn, an.y));
            lastw[e * 32 + bp]     = (1.0f - z0) * n0;
            lastw[e * 32 + bp + 1] = (1.0f - z1) * n1;
        }
        __syncthreads();
        // fc2: reads lastw/f2t only. All fc2 reads complete before any GRU2(t+1)
        // write to lastw (ordered by the GRU1/GRU2 sync of t+1) -> no trailing sync.
        if (tid < 512) {
            int b = tid >> 4, kk0 = (tid & 15) * 4;
            float4 acc = *(const float4*)(fc2_b + kk0);
            #pragma unroll 5
            for (int e = 0; e < EE; e++) {
                float a = lastw[e * 32 + b];
                float4 wv = *(const float4*)(f2t + e * KV + kk0);
                acc.x = fmaf(wv.x, a, acc.x);
                acc.y = fmaf(wv.y, a, acc.y);
                acc.z = fmaf(wv.z, a, acc.z);
                acc.w = fmaf(wv.w, a, acc.w);
            }
            *(float4*)(out + PRED_OFF + ((size_t)(bg0 + b) * TT + t) * KV + kk0) = acc;
        }
    }
}

extern "C" void kernel_launch(void* const* d_in, const int* in_sizes, int n_in,
                              void* d_out, int out_size) {
    (void)in_sizes; (void)n_in; (void)out_size;
    const int*   x       = (const int*)  d_in[0];
    const float* emb     = (const float*)d_in[1];
    const float* eW_ih0  = (const float*)d_in[2];
    const float* eW_hh0  = (const float*)d_in[3];
    const float* eb_ih0  = (const float*)d_in[4];
    const float* eb_hh0  = (const float*)d_in[5];
    const float* eW_ih1  = (const float*)d_in[6];
    const float* eW_hh1  = (const float*)d_in[7];
    const float* eb_ih1  = (const float*)d_in[8];
    const float* eb_hh1  = (const float*)d_in[9];
    const float* dW_ih0  = (const float*)d_in[10];
    const float* db_ih0  = (const float*)d_in[12];
    const float* db_hh0  = (const float*)d_in[13];
    const float* dW_ih1  = (const float*)d_in[14];
    const float* db_ih1  = (const float*)d_in[16];
    const float* db_hh1  = (const float*)d_in[17];
    const float* fc11_w  = (const float*)d_in[18];
    const float* fc11_b  = (const float*)d_in[19];
    const float* fc12_w  = (const float*)d_in[20];
    const float* fc12_b  = (const float*)d_in[21];
    const float* p1_w    = (const float*)d_in[22];
    const float* p1_b    = (const float*)d_in[23];
    const float* p2_w    = (const float*)d_in[24];
    const float* p2_b    = (const float*)d_in[25];
    const float* fc2_w   = (const float*)d_in[26];
    const float* fc2_b   = (const float*)d_in[27];
    const float* eps     = (const float*)d_in[28];

    {
        int maxtot = NTILES * NPH * 32;  // 16800
        dim3 grid((maxtot + 255) / 256, 4);
        pack_b16<<<grid, 256>>>(eW_ih0, eW_hh0, eW_ih1, eW_hh1);
    }

    cudaFuncSetAttribute((const void*)vae_all,
                         cudaFuncAttributeMaxDynamicSharedMemorySize,
                         SMEM_FLOATS * (int)sizeof(float));

    vae_all<<<NCTA, NTH, SMEM_FLOATS * sizeof(float)>>>(
        x, emb, eb_ih0, eb_hh0, eb_ih1, eb_hh1,
        dW_ih0, db_ih0, db_hh0, dW_ih1, db_ih1, db_hh1,
        fc11_w, fc11_b, fc12_w, fc12_b, p1_w, p1_b, p2_w, p2_b,
        fc2_w, fc2_b, eps, (float*)d_out);
}